// round 13
// baseline (speedup 1.0000x reference)
#include <cuda_runtime.h>
#include <cuda_bf16.h>
#include <math.h>
#include <stdint.h>

#define TT   2048
#define DD   2048
#define NHH  16
#define DHH  128
#define FFD  5632
#define SS   TT
#define QKD  6528   // 3*DD + 256 + 128 (qkv | dw1-hidden | dd)

// ---------------- scratch (static device globals; no allocation) ----------
static __device__ float g_qkv[(size_t)TT*QKD];   // qkv | dwh(raw) | ddv(raw)
static __device__ float g_v  [(size_t)NHH*TT*DHH];  // v; later softmax tile partials
static __device__ float g_lg [(size_t)NHH*TT*SS];   // logits; later PV split-K partials
static __device__ float g_w  [(size_t)TT*256];
static __device__ float g_h  [(size_t)TT*DD];
static __device__ float g_mstat[(size_t)NHH*TT];
static __device__ float g_istat[(size_t)NHH*TT];

// bf16 split operands
static __device__ __nv_bfloat16 g_wallT_h[(size_t)QKD*DD];  // rows 6464..6527 stay zero
static __device__ __nv_bfloat16 g_wallT_l[(size_t)QKD*DD];
static __device__ __nv_bfloat16 g_woT_h  [(size_t)DD*DD];
static __device__ __nv_bfloat16 g_woT_l  [(size_t)DD*DD];
static __device__ __nv_bfloat16 g_w13T_h [(size_t)2*FFD*DD]; // interleaved: even=w1, odd=w3
static __device__ __nv_bfloat16 g_w13T_l [(size_t)2*FFD*DD];
static __device__ __nv_bfloat16 g_w2fT_h [(size_t)DD*FFD];
static __device__ __nv_bfloat16 g_w2fT_l [(size_t)DD*FFD];
static __device__ __nv_bfloat16 g_act_h  [(size_t)TT*FFD];
static __device__ __nv_bfloat16 g_act_l  [(size_t)TT*FFD];
static __device__ __nv_bfloat16 g_qh [(size_t)NHH*TT*DHH];
static __device__ __nv_bfloat16 g_ql [(size_t)NHH*TT*DHH];
static __device__ __nv_bfloat16 g_kh [(size_t)NHH*TT*DHH];
static __device__ __nv_bfloat16 g_kl [(size_t)NHH*TT*DHH];
static __device__ __nv_bfloat16 g_vT_h[(size_t)NHH*DHH*TT];
static __device__ __nv_bfloat16 g_vT_l[(size_t)NHH*DHH*TT];
static __device__ __nv_bfloat16 g_ph [(size_t)NHH*TT*SS];   // also reused as FFN act2_h
static __device__ __nv_bfloat16 g_pl [(size_t)NHH*TT*SS];   // also reused as FFN act2_l

// =================== asm helpers (plain-sm_103-legal) =======================
__device__ __forceinline__ uint32_t smem_u32(const void* p) {
    uint32_t a;
    asm("{ .reg .u64 t; cvta.to.shared.u64 t, %1; cvt.u32.u64 %0, t; }" : "=r"(a) : "l"(p));
    return a;
}
template<int NN> __device__ __forceinline__ void cp_wait() {
    asm volatile("cp.async.wait_group %0;" :: "n"(NN) : "memory");
}
__device__ __forceinline__ void cp_commit() {
    asm volatile("cp.async.commit_group;" ::: "memory");
}
__device__ __forceinline__ void cp16(uint32_t dst, const void* src) {
    asm volatile("cp.async.cg.shared.global [%0], [%1], 16;" :: "r"(dst), "l"(src) : "memory");
}
__device__ __forceinline__ void ldsm4(uint32_t* r, uint32_t addr) {
    asm volatile("ldmatrix.sync.aligned.m8n8.x4.shared.b16 {%0,%1,%2,%3}, [%4];"
                 : "=r"(r[0]), "=r"(r[1]), "=r"(r[2]), "=r"(r[3]) : "r"(addr));
}
__device__ __forceinline__ void mma_bf16(float* c, const uint32_t* a, const uint32_t* b) {
    asm volatile(
        "mma.sync.aligned.m16n8k16.row.col.f32.bf16.bf16.f32 "
        "{%0,%1,%2,%3}, {%4,%5,%6,%7}, {%8,%9}, {%0,%1,%2,%3};"
        : "+f"(c[0]), "+f"(c[1]), "+f"(c[2]), "+f"(c[3])
        : "r"(a[0]), "r"(a[1]), "r"(a[2]), "r"(a[3]), "r"(b[0]), "r"(b[1]));
}
#define SWZ(o) ((o) ^ (((o) >> 3) & 0x30))

__device__ __forceinline__ void split2(float2 v, __nv_bfloat162* hi, __nv_bfloat162* lo) {
    __nv_bfloat16 hx = __float2bfloat16(v.x), hy = __float2bfloat16(v.y);
    hi->x = hx; hi->y = hy;
    lo->x = __float2bfloat16(v.x - __bfloat162float(hx));
    lo->y = __float2bfloat16(v.y - __bfloat162float(hy));
}

// =================== mma.sync split-bf16 GEMM ================================
// MODE 0: plain  MODE 1: causal skip (logits)  MODE 3: GLU epilogue
// MODE 4: split-K causal PV (fp32 partials)
#define MM_STAGE 32768
#define MM_SMEM  (3 * MM_STAGE)

template<int MODE>
__global__ void __launch_bounds__(256, 2) mma_gemm(
    const __nv_bfloat16* __restrict__ Ahi, const __nv_bfloat16* __restrict__ Alo,
    const __nv_bfloat16* __restrict__ Bhi, const __nv_bfloat16* __restrict__ Blo,
    float* __restrict__ C, const float* __restrict__ R,
    __nv_bfloat16* __restrict__ Chi, __nv_bfloat16* __restrict__ Clo,
    int M, int N, int K, int ldc,
    long long sA, long long sB, long long sC, long long sX)
{
    const int bm = blockIdx.y * 128;
    const int bn = (MODE == 4) ? 0 : blockIdx.x * 128;
    const int kx = (MODE == 4) ? blockIdx.x : 0;
    if (MODE == 1 && bn > bm) return;

    extern __shared__ __align__(1024) char sm[];
    const int tid = threadIdx.x, lane = tid & 31, wid = tid >> 5;
    const int wm = wid & 3, wn = wid >> 2;
    const uint32_t sbase = smem_u32(sm);
    const long long z = blockIdx.z;
    Ahi += z * sA; Alo += z * sA;
    Bhi += z * sB; Blo += z * sB;
    C   += z * sC;
    if (MODE == 4) C += (long long)kx * sX;
    if (R)   R   += z * sC;
    if (Chi) { Chi += z * sC; Clo += z * sC; }

    const __nv_bfloat16* srcs[4] = {Ahi, Alo, Bhi, Blo};
    const int rowbase[4] = {bm, bm, bn, bn};

    auto issue = [&](int kc, int s) {
        #pragma unroll
        for (int i = 0; i < 8; i++) {
            int idx = tid + i * 256;
            int buf = idx >> 9, cc = idx & 511, row = cc >> 2, cb = cc & 3;
            const __nv_bfloat16* src =
                srcs[buf] + (size_t)(rowbase[buf] + row) * K + kc * 32 + cb * 8;
            uint32_t dst = sbase + s * MM_STAGE + buf * 8192 + SWZ(row * 64 + cb * 16);
            cp16(dst, src);
        }
        cp_commit();
    };

    float acc[2][8][4];
    #pragma unroll
    for (int a = 0; a < 2; a++)
        #pragma unroll
        for (int b = 0; b < 8; b++)
            #pragma unroll
            for (int q = 0; q < 4; q++) acc[a][b][q] = 0.f;

    const int Keff = (MODE == 4) ? ((bm + 128 < K) ? bm + 128 : K) : K;
    const int NC = Keff >> 5;
    int cBeg = 0, cEnd = NC;
    if (MODE == 4) {
        const int half = NC >> 1;
        cBeg = kx ? half : 0;
        cEnd = kx ? NC : half;
    }
    issue(cBeg, 0);

    int s = 0;
    for (int c = cBeg; c < cEnd; c++) {
        if (c + 1 < cEnd) { issue(c + 1, (s == 2) ? 0 : s + 1); cp_wait<1>(); }
        else              { cp_wait<0>(); }
        __syncthreads();

        const uint32_t aB = sbase + s * MM_STAGE;
        const uint32_t bB = aB + 16384;
        #pragma unroll
        for (int ks = 0; ks < 2; ks++) {
            uint32_t ah[2][4], al[2][4];
            #pragma unroll
            for (int mt = 0; mt < 2; mt++) {
                int row = wm * 32 + mt * 16 + (lane & 15);
                uint32_t off = SWZ((uint32_t)(row * 64 + ks * 32 + ((lane >> 4) << 4)));
                ldsm4(ah[mt], aB + off);
                ldsm4(al[mt], aB + 8192 + off);
            }
            #pragma unroll
            for (int np = 0; np < 4; np++) {
                int rowb = wn * 64 + np * 16 + (lane & 7) + ((lane >> 4) << 3);
                uint32_t offb = SWZ((uint32_t)(rowb * 64 + ks * 32 + (((lane >> 3) & 1) << 4)));
                uint32_t bh[4], bl[4];
                ldsm4(bh, bB + offb);
                ldsm4(bl, bB + 8192 + offb);
                #pragma unroll
                for (int sub = 0; sub < 2; sub++) {
                    const int nt = np * 2 + sub;
                    #pragma unroll
                    for (int mt = 0; mt < 2; mt++) {
                        mma_bf16(acc[mt][nt], ah[mt], bh + sub * 2);
                        mma_bf16(acc[mt][nt], ah[mt], bl + sub * 2);
                        mma_bf16(acc[mt][nt], al[mt], bh + sub * 2);
                    }
                }
            }
        }
        s = (s == 2) ? 0 : s + 1;
    }

    #pragma unroll
    for (int mt = 0; mt < 2; mt++) {
        int r0 = bm + wm * 32 + mt * 16 + (lane >> 2);
        #pragma unroll
        for (int nt = 0; nt < 8; nt++) {
            if (MODE == 3) {
                int f = (bn >> 1) + wn * 32 + nt * 4 + (lane & 3);
                float a0 = acc[mt][nt][0], b0 = acc[mt][nt][1];
                float a1 = acc[mt][nt][2], b1 = acc[mt][nt][3];
                float v0 = (a0 / (1.f + __expf(-a0))) * b0;
                float v1 = (a1 / (1.f + __expf(-a1))) * b1;
                size_t i0 = (size_t)r0 * ldc + f;
                size_t i1 = i0 + 8 * (size_t)ldc;
                __nv_bfloat16 h0 = __float2bfloat16(v0);
                __nv_bfloat16 h1 = __float2bfloat16(v1);
                Chi[i0] = h0; Clo[i0] = __float2bfloat16(v0 - __bfloat162float(h0));
                Chi[i1] = h1; Clo[i1] = __float2bfloat16(v1 - __bfloat162float(h1));
                continue;
            }
            int col = bn + wn * 64 + nt * 8 + (lane & 3) * 2;
            size_t i0 = (size_t)r0 * ldc + col;
            size_t i1 = i0 + 8 * (size_t)ldc;
            float2 v0 = {acc[mt][nt][0], acc[mt][nt][1]};
            float2 v1 = {acc[mt][nt][2], acc[mt][nt][3]};
            if (MODE != 4 && Chi) {
                __nv_bfloat162 h0, l0, h1, l1;
                split2(v0, &h0, &l0);
                split2(v1, &h1, &l1);
                *(__nv_bfloat162*)(Chi + i0) = h0;
                *(__nv_bfloat162*)(Clo + i0) = l0;
                *(__nv_bfloat162*)(Chi + i1) = h1;
                *(__nv_bfloat162*)(Clo + i1) = l1;
            } else {
                if (R) {
                    float2 a = *(const float2*)(R + i0);
                    float2 b = *(const float2*)(R + i1);
                    v0.x += a.x; v0.y += a.y; v1.x += b.x; v1.y += b.y;
                }
                *(float2*)(C + i0) = v0;
                *(float2*)(C + i1) = v1;
            }
        }
    }
}

// PV split-K combine: act[t][h*128+d] = split(P0[h][t][d] + P1[h][t][d])
__global__ void pv_combine(const float* __restrict__ P,
                           __nv_bfloat16* __restrict__ hi, __nv_bfloat16* __restrict__ lo)
{
    long long i = (long long)blockIdx.x * 256 + threadIdx.x;
    const long long TOT = (long long)NHH * TT * DHH;
    if (i < TOT) {
        float v = P[i] + P[i + TOT];
        long long h = i / ((long long)TT * DHH);
        long long r = i - h * (long long)TT * DHH;
        long long t = r / DHH, d = r - t * DHH;
        size_t o = (size_t)t * DD + h * DHH + d;
        __nv_bfloat16 hv = __float2bfloat16(v);
        hi[o] = hv;
        lo[o] = __float2bfloat16(v - __bfloat162float(hv));
    }
}

// =================== conversion kernels =====================================
__global__ void convT(const float* __restrict__ W, __nv_bfloat16* __restrict__ hi,
                      __nv_bfloat16* __restrict__ lo, int K, int N,
                      long long sW, long long sO, int rmul, int radd)
{
    W  += (long long)blockIdx.z * sW;
    hi += (long long)blockIdx.z * sO;
    lo += (long long)blockIdx.z * sO;
    __shared__ float t[32][33];
    int n0 = blockIdx.x * 32, k0 = blockIdx.y * 32;
    int x = threadIdx.x, y = threadIdx.y;
    #pragma unroll
    for (int yy = y; yy < 32; yy += 8)
        t[yy][x] = W[(size_t)(k0 + yy) * N + n0 + x];
    __syncthreads();
    #pragma unroll
    for (int yy = y; yy < 32; yy += 8) {
        float v = t[x][yy];
        __nv_bfloat16 h = __float2bfloat16(v);
        size_t o = ((size_t)(n0 + yy) * rmul + radd) * K + k0 + x;
        hi[o] = h;
        lo[o] = __float2bfloat16(v - __bfloat162float(h));
    }
}

// =================== fused SIMT kernels =====================================
__global__ void rmsnorm_split(const float* __restrict__ x, const float* __restrict__ w,
                              __nv_bfloat16* __restrict__ hi, __nv_bfloat16* __restrict__ lo,
                              int d)
{
    long long t = blockIdx.x;
    const float* r = x + t * (long long)d;
    int tid = threadIdx.x;
    float ss = 0.f;
    for (int i = tid; i < d; i += blockDim.x) { float v = r[i]; ss += v * v; }
    for (int off = 16; off > 0; off >>= 1) ss += __shfl_xor_sync(0xffffffffu, ss, off);
    __shared__ float sh[8];
    if ((tid & 31) == 0) sh[tid >> 5] = ss;
    __syncthreads();
    float tot = 0.f;
    #pragma unroll
    for (int i = 0; i < 8; i++) tot += sh[i];
    float inv = rsqrtf(tot / d + 1e-6f);
    for (int i = tid; i < d; i += blockDim.x) {
        float v = r[i] * inv * w[i];
        __nv_bfloat16 h = __float2bfloat16(v);
        hi[t * (long long)d + i] = h;
        lo[t * (long long)d + i] = __float2bfloat16(v - __bfloat162float(h));
    }
}

// qkv split + head rmsnorm + rope; reads fused qkv|dwh|ddv rows (stride QKD)
__global__ void qkv_prep(const float* __restrict__ qkv,
                         const float* __restrict__ qw, const float* __restrict__ kw,
                         __nv_bfloat16* __restrict__ qh, __nv_bfloat16* __restrict__ ql,
                         __nv_bfloat16* __restrict__ kh, __nv_bfloat16* __restrict__ kl,
                         float* __restrict__ v)
{
    int n = blockIdx.x, t = blockIdx.y, d = threadIdx.x;
    const float* rowp = qkv + (long long)t * QKD + n * DHH;
    float qv = rowp[d], kv = rowp[DD + d], vv = rowp[2 * DD + d];

    float sq = qv * qv, sk = kv * kv;
    for (int off = 16; off > 0; off >>= 1) {
        sq += __shfl_xor_sync(0xffffffffu, sq, off);
        sk += __shfl_xor_sync(0xffffffffu, sk, off);
    }
    __shared__ float rq[4], rk[4];
    if ((d & 31) == 0) { rq[d >> 5] = sq; rk[d >> 5] = sk; }
    __syncthreads();
    float vq = (rq[0] + rq[1] + rq[2] + rq[3]) / (float)DHH;
    float vk = (rk[0] + rk[1] + rk[2] + rk[3]) / (float)DHH;
    float qn = qv * rsqrtf(vq + 1e-6f) * qw[d];
    float kn = kv * rsqrtf(vk + 1e-6f) * kw[d];

    __shared__ float sqb[DHH], skb[DHH];
    sqb[d] = qn; skb[d] = kn;
    __syncthreads();

    long long base = ((long long)n * TT + t) * DHH;
    v[base + d] = vv;
    if (d < 64) {
        float inv = powf(10000.f, -((float)d) / 64.f);
        float ang = (float)t * inv;
        float c, s;
        sincosf(ang, &s, &c);
        float q1 = sqb[d], q2 = sqb[64 + d];
        float k1 = skb[d], k2 = skb[64 + d];
        const float sc = 0.08838834764831845f;
        float qo0 = (q1 * c - q2 * s) * sc, qo1 = (q2 * c + q1 * s) * sc;
        float ko0 = (k1 * c - k2 * s),      ko1 = (k2 * c + k1 * s);
        __nv_bfloat16 h;
        h = __float2bfloat16(qo0); qh[base + 2*d]   = h; ql[base + 2*d]   = __float2bfloat16(qo0 - __bfloat162float(h));
        h = __float2bfloat16(qo1); qh[base + 2*d+1] = h; ql[base + 2*d+1] = __float2bfloat16(qo1 - __bfloat162float(h));
        h = __float2bfloat16(ko0); kh[base + 2*d]   = h; kl[base + 2*d]   = __float2bfloat16(ko0 - __bfloat162float(h));
        h = __float2bfloat16(ko1); kh[base + 2*d+1] = h; kl[base + 2*d+1] = __float2bfloat16(ko1 - __bfloat162float(h));
    }
}

// w projection; reads RAW dwh (pre-gelu) at qkvb cols [6144,6400), stride QKD
__global__ void wproj_k(const float* __restrict__ dwh_raw, const float* __restrict__ qkw,
                        float* __restrict__ w)
{
    int t = blockIdx.x;
    int tid = threadIdx.x;
    __shared__ float sh[256];
    {
        float xg = dwh_raw[(long long)t * QKD + tid];
        sh[tid] = 0.5f * xg * (1.f + erff(xg * 0.7071067811865475f));
    }
    __syncthreads();
    int c = tid >> 6, r = tid & 63, i = r >> 4, n = r & 15;
    float acc = 0.f;
    #pragma unroll 8
    for (int kk = 0; kk < 64; kk++)
        acc += sh[c * 64 + kk] * qkw[((c * 64 + kk) * 4 + i) * 16 + n];
    __shared__ float sw[256];
    sw[tid] = acc;
    __syncthreads();
    float out = acc;
    if (i < 2) {
        float ss = 0.f;
        #pragma unroll
        for (int m = 0; m < 16; m++) { float vv = sw[c * 64 + i * 16 + m]; ss += vv * vv; }
        out = acc * rsqrtf(ss / 16.f + 1e-6f);
    }
    w[(long long)t * 256 + tid] = out;
}

// cross_head_proj.
// POST=0: in-place on X, lower-triangle tiles; ALSO emits per-(n,row,tile)
//         partial softmax stats (max, sumexp) into Pm/Ps.
// POST=1: reads mixed logits, applies exp(x-m)*inv via mstat/istat, mixes,
//         writes bf16 split ph/pl; tiles up to 128-block edge of t.
template<int POST>
__global__ void crosshead_k(float* __restrict__ X, const float* __restrict__ W,
                            const float* __restrict__ ddv_raw,
                            int cq, int ck, int qoff, int koff,
                            __nv_bfloat16* __restrict__ ph, __nv_bfloat16* __restrict__ pl,
                            float* __restrict__ Pm, float* __restrict__ Ps,
                            const float* __restrict__ mstat, const float* __restrict__ istat)
{
    if (POST == 0) { if (blockIdx.x > blockIdx.y) return; }
    else           { if ((blockIdx.x >> 2) > (blockIdx.y >> 2)) return; }
    __shared__ float q1[32][2][16], q2[32][2][16], qd[32][16];
    __shared__ float k1[32][2][16], k2[32][2][16], kd[32][16];
    __shared__ float ms[32][16], is_[32][16];
    int s0 = blockIdx.x * 32, t0 = blockIdx.y * 32;
    int tid = threadIdx.x;

    for (int idx = tid; idx < 32 * 64; idx += 256) {
        int row = idx >> 6, r = idx & 63;
        int i = r >> 4, n = r & 15;
        float vq = W[(long long)(t0 + row) * 256 + cq * 64 + i * 16 + n];
        float vk = W[(long long)(s0 + row) * 256 + ck * 64 + i * 16 + n];
        if (i < 2) { q1[row][i][n] = vq; k1[row][i][n] = vk; }
        else       { q2[row][i - 2][n] = vq; k2[row][i - 2][n] = vk; }
    }
    for (int idx = tid; idx < 32 * 16; idx += 256) {
        int row = idx >> 4, n = idx & 15;
        qd[row][n] = tanhf(ddv_raw[(long long)(t0 + row) * QKD + qoff + n]);
        kd[row][n] = tanhf(ddv_raw[(long long)(s0 + row) * QKD + koff + n]);
        if (POST == 1) {
            ms[row][n]  = mstat[(long long)n * TT + t0 + row];
            is_[row][n] = istat[(long long)n * TT + t0 + row];
        }
    }
    __syncthreads();

    const long long TSs = (long long)TT * SS;
    int si = tid & 31;
    int s = s0 + si;
    for (int tt = (tid >> 5); tt < 32; tt += 8) {
        int tg = t0 + tt;
        bool valid = (s <= tg);
        long long base = (long long)tg * SS + s;
        float xv[16];
        #pragma unroll
        for (int n = 0; n < 16; n++) {
            float raw = X[n * TSs + base];
            if (POST == 0) xv[n] = raw;
            else           xv[n] = valid ? __expf(raw - ms[tt][n]) * is_[tt][n] : 0.f;
        }
        float a0 = 0.f, a1 = 0.f, b0 = 0.f, b1 = 0.f;
        #pragma unroll
        for (int n = 0; n < 16; n++) {
            a0 += xv[n] * q1[tt][0][n];
            a1 += xv[n] * q1[tt][1][n];
            b0 += xv[n] * k1[si][0][n];
            b1 += xv[n] * k1[si][1][n];
        }
        float ovv[16];
        #pragma unroll
        for (int n = 0; n < 16; n++) {
            float ov = xv[n] * (1.f + qd[tt][n] + kd[si][n])
                     + a0 * q2[tt][0][n] + a1 * q2[tt][1][n]
                     + b0 * k2[si][0][n] + b1 * k2[si][1][n];
            ovv[n] = ov;
            if (POST == 0) {
                X[n * TSs + base] = ov;
            } else {
                __nv_bfloat16 h = __float2bfloat16(ov);
                ph[n * TSs + base] = h;
                pl[n * TSs + base] = __float2bfloat16(ov - __bfloat162float(h));
            }
        }
        if (POST == 0) {
            // per-(n, row tg, s-tile) partial stats via warp reduction
            #pragma unroll
            for (int n = 0; n < 16; n++) {
                float mv = valid ? ovv[n] : -3.4e38f;
                #pragma unroll
                for (int off = 16; off > 0; off >>= 1)
                    mv = fmaxf(mv, __shfl_xor_sync(0xffffffffu, mv, off));
                float e = valid ? __expf(ovv[n] - mv) : 0.f;
                #pragma unroll
                for (int off = 16; off > 0; off >>= 1)
                    e += __shfl_xor_sync(0xffffffffu, e, off);
                if (si == 0) {
                    size_t pi = ((size_t)n * TT + tg) * 64 + blockIdx.x;
                    Pm[pi] = mv;
                    Ps[pi] = e;
                }
            }
        }
    }
}

// merge <=64 tile partials per (head,row) -> global max + 1/sum
__global__ void softmax_combine(const float* __restrict__ Pm, const float* __restrict__ Ps,
                                float* __restrict__ mstat, float* __restrict__ istat)
{
    int t = blockIdx.x, n = blockIdx.y, lane = threadIdx.x;   // 32 threads
    int ntiles = (t >> 5) + 1;
    size_t base = ((size_t)n * TT + t) * 64;
    float m0 = (lane < ntiles)      ? Pm[base + lane]      : -3.4e38f;
    float m1 = (lane + 32 < ntiles) ? Pm[base + lane + 32] : -3.4e38f;
    float s0 = (lane < ntiles)      ? Ps[base + lane]      : 0.f;
    float s1 = (lane + 32 < ntiles) ? Ps[base + lane + 32] : 0.f;
    float mm = fmaxf(m0, m1);
    #pragma unroll
    for (int off = 16; off > 0; off >>= 1)
        mm = fmaxf(mm, __shfl_xor_sync(0xffffffffu, mm, off));
    float ss = s0 * __expf(m0 - mm) + s1 * __expf(m1 - mm);
    #pragma unroll
    for (int off = 16; off > 0; off >>= 1)
        ss += __shfl_xor_sync(0xffffffffu, ss, off);
    if (lane == 0) {
        mstat[(size_t)n * TT + t] = mm;
        istat[(size_t)n * TT + t] = 1.f / ss;
    }
}

// =================== host orchestration =====================================
extern "C" void kernel_launch(void* const* d_in, const int* in_sizes, int n_in,
                              void* d_out, int out_size)
{
    const float* x       = (const float*)d_in[0];
    const float* attn_nw = (const float*)d_in[1];
    const float* wqkv    = (const float*)d_in[2];
    const float* q_nw    = (const float*)d_in[3];
    const float* k_nw    = (const float*)d_in[4];
    const float* dw1     = (const float*)d_in[5];
    const float* qkw     = (const float*)d_in[6];
    const float* dd      = (const float*)d_in[7];
    const float* wo      = (const float*)d_in[8];
    const float* ffn_nw  = (const float*)d_in[9];
    const float* w1f     = (const float*)d_in[10];
    const float* w3f     = (const float*)d_in[11];
    const float* w2f     = (const float*)d_in[12];
    float* out = (float*)d_out;

    static float *qkvb = nullptr, *v, *lg, *w, *h, *mstat, *istat;
    static __nv_bfloat16 *wallT_h, *wallT_l, *woT_h, *woT_l, *w13T_h, *w13T_l,
                         *w2fT_h, *w2fT_l, *act_h, *act_l,
                         *qh, *ql, *kh, *kl, *vT_h, *vT_l, *ph, *pl;
    if (!qkvb) {
        cudaGetSymbolAddress((void**)&qkvb, g_qkv);
        cudaGetSymbolAddress((void**)&v,    g_v);
        cudaGetSymbolAddress((void**)&lg,   g_lg);
        cudaGetSymbolAddress((void**)&w,    g_w);
        cudaGetSymbolAddress((void**)&h,    g_h);
        cudaGetSymbolAddress((void**)&mstat, g_mstat);
        cudaGetSymbolAddress((void**)&istat, g_istat);
        cudaGetSymbolAddress((void**)&wallT_h, g_wallT_h);
        cudaGetSymbolAddress((void**)&wallT_l, g_wallT_l);
        cudaGetSymbolAddress((void**)&woT_h,   g_woT_h);
        cudaGetSymbolAddress((void**)&woT_l,   g_woT_l);
        cudaGetSymbolAddress((void**)&w13T_h,  g_w13T_h);
        cudaGetSymbolAddress((void**)&w13T_l,  g_w13T_l);
        cudaGetSymbolAddress((void**)&w2fT_h,  g_w2fT_h);
        cudaGetSymbolAddress((void**)&w2fT_l,  g_w2fT_l);
        cudaGetSymbolAddress((void**)&act_h,   g_act_h);
        cudaGetSymbolAddress((void**)&act_l,   g_act_l);
        cudaGetSymbolAddress((void**)&qh,   g_qh);
        cudaGetSymbolAddress((void**)&ql,   g_ql);
        cudaGetSymbolAddress((void**)&kh,   g_kh);
        cudaGetSymbolAddress((void**)&kl,   g_kl);
        cudaGetSymbolAddress((void**)&vT_h, g_vT_h);
        cudaGetSymbolAddress((void**)&vT_l, g_vT_l);
        cudaGetSymbolAddress((void**)&ph,   g_ph);
        cudaGetSymbolAddress((void**)&pl,   g_pl);
        cudaFuncSetAttribute(mma_gemm<0>, cudaFuncAttributeMaxDynamicSharedMemorySize, MM_SMEM);
        cudaFuncSetAttribute(mma_gemm<1>, cudaFuncAttributeMaxDynamicSharedMemorySize, MM_SMEM);
        cudaFuncSetAttribute(mma_gemm<3>, cudaFuncAttributeMaxDynamicSharedMemorySize, MM_SMEM);
        cudaFuncSetAttribute(mma_gemm<4>, cudaFuncAttributeMaxDynamicSharedMemorySize, MM_SMEM);
    }

    dim3 tb(32, 8);
    // weight conversions (w1f -> even rows, w3f -> odd rows of w13T)
    convT<<<dim3(3 * DD / 32, DD / 32), tb>>>(wqkv, wallT_h, wallT_l, DD, 3 * DD, 0, 0, 1, 0);
    convT<<<dim3(256 / 32, DD / 32), tb>>>(dw1, wallT_h + (size_t)3 * DD * DD,
                                           wallT_l + (size_t)3 * DD * DD, DD, 256, 0, 0, 1, 0);
    convT<<<dim3(64 / 32, DD / 32), tb>>>(dd, wallT_h + (size_t)(3 * DD + 256) * DD,
                                          wallT_l + (size_t)(3 * DD + 256) * DD, DD, 64, 0, 0, 1, 0);
    convT<<<dim3(DD / 32, DD / 32), tb>>>(wo,  woT_h,  woT_l,  DD, DD, 0, 0, 1, 0);
    convT<<<dim3(FFD / 32, DD / 32), tb>>>(w1f, w13T_h, w13T_l, DD, FFD, 0, 0, 2, 0);
    convT<<<dim3(FFD / 32, DD / 32), tb>>>(w3f, w13T_h, w13T_l, DD, FFD, 0, 0, 2, 1);
    convT<<<dim3(DD / 32, FFD / 32), tb>>>(w2f, w2fT_h, w2fT_l, FFD, DD, 0, 0, 1, 0);

    // 1. hn = rmsnorm(x) -> split act
    rmsnorm_split<<<TT, 256>>>(x, attn_nw, act_h, act_l, DD);
    // 2. [qkv | dwh | ddv] = hn @ [wqkv | dw1 | dd]   (one merged GEMM)
    mma_gemm<0><<<dim3(QKD / 128, TT / 128), 256, MM_SMEM>>>(
        act_h, act_l, wallT_h, wallT_l, qkvb, nullptr, nullptr, nullptr,
        TT, QKD, DD, QKD, 0, 0, 0, 0);
    // 3. split + head rmsnorm + rope ; v fp32 then transpose-split
    qkv_prep<<<dim3(NHH, TT), 128>>>(qkvb, q_nw, k_nw, qh, ql, kh, kl, v);
    convT<<<dim3(DHH / 32, TT / 32, NHH), tb>>>(v, vT_h, vT_l, TT, DHH,
        (long long)TT * DHH, (long long)DHH * TT, 1, 0);
    // 4. dyn weights: gelu fused into wproj; tanh fused into crosshead loads
    wproj_k<<<TT, 256>>>(qkvb + 3 * DD, qkw, w);
    // 5. logits = q @ k^T (causal tiles only)
    mma_gemm<1><<<dim3(TT / 128, TT / 128, NHH), 256, MM_SMEM>>>(
        qh, ql, kh, kl, lg, nullptr, nullptr, nullptr, TT, TT, DHH, SS,
        (long long)TT * DHH, (long long)TT * DHH, (long long)TT * SS, 0);
    // 6. cross_head pre (in-place, emits partial softmax stats into dead g_v)
    {
        float* Pm = v;
        float* Ps = v + (size_t)NHH * TT * 64;
        crosshead_k<0><<<dim3(SS / 32, TT / 32), 256>>>(
            lg, w, qkvb + 3 * DD + 256, 0, 1, 0, 16, nullptr, nullptr,
            Pm, Ps, nullptr, nullptr);
        // 7. combine tile partials -> global stats
        softmax_combine<<<dim3(TT, NHH), 32>>>(Pm, Ps, mstat, istat);
    }
    // 8. cross_head post: inline softmax apply + mix -> split ph/pl
    crosshead_k<1><<<dim3(SS / 32, TT / 32), 256>>>(
        lg, w, qkvb + 3 * DD + 256, 2, 3, 32, 48, ph, pl,
        nullptr, nullptr, mstat, istat);
    // 9. o = probs @ v, 2-way split-K (fp32 partials into dead lg), then combine
    mma_gemm<4><<<dim3(2, TT / 128, NHH), 256, MM_SMEM>>>(
        ph, pl, vT_h, vT_l, lg, nullptr, nullptr, nullptr, TT, DHH, TT, DHH,
        (long long)TT * SS, (long long)DHH * TT, (long long)TT * DHH,
        (long long)NHH * TT * DHH);
    pv_combine<<<(int)(((long long)NHH * TT * DHH + 255) / 256), 256>>>(lg, act_h, act_l);
    // 10. h = x + o @ wo
    mma_gemm<0><<<dim3(DD / 128, TT / 128), 256, MM_SMEM>>>(
        act_h, act_l, woT_h, woT_l, h, x, nullptr, nullptr, TT, DD, DD, DD, 0, 0, 0, 0);
    // 11. ffn: rmsnorm->split(act), interleaved w1|w3 gemm + fused swiglu
    //     -> split act2 (ph/pl scratch, DISJOINT from A), then w2 gemm
    rmsnorm_split<<<TT, 256>>>(h, ffn_nw, act_h, act_l, DD);
    mma_gemm<3><<<dim3(2 * FFD / 128, TT / 128), 256, MM_SMEM>>>(
        act_h, act_l, w13T_h, w13T_l, nullptr, nullptr, ph, pl,
        TT, 2 * FFD, DD, FFD, 0, 0, 0, 0);
    mma_gemm<0><<<dim3(DD / 128, TT / 128), 256, MM_SMEM>>>(
        ph, pl, w2fT_h, w2fT_l, out, h, nullptr, nullptr, TT, DD, FFD, DD, 0, 0, 0, 0);
}

// round 14
// speedup vs baseline: 1.0936x; 1.0936x over previous
#include <cuda_runtime.h>
#include <cuda_bf16.h>
#include <math.h>
#include <stdint.h>

#define TT   2048
#define DD   2048
#define NHH  16
#define DHH  128
#define FFD  5632
#define SS   TT
#define QKD  6528   // 3*DD + 256 + 128 (qkv | dw1-hidden | dd)

// ---------------- scratch (static device globals; no allocation) ----------
static __device__ float g_qkv[(size_t)TT*QKD];   // qkv | dwh(raw) | ddv(raw)
static __device__ float g_v  [(size_t)NHH*TT*DHH];
static __device__ float g_lg [(size_t)NHH*TT*SS];   // logits; later PV split-K partials
static __device__ float g_w  [(size_t)TT*256];
static __device__ float g_h  [(size_t)TT*DD];

// bf16 split operands
static __device__ __nv_bfloat16 g_wallT_h[(size_t)QKD*DD];  // rows 6464..6527 stay zero
static __device__ __nv_bfloat16 g_wallT_l[(size_t)QKD*DD];
static __device__ __nv_bfloat16 g_woT_h  [(size_t)DD*DD];
static __device__ __nv_bfloat16 g_woT_l  [(size_t)DD*DD];
static __device__ __nv_bfloat16 g_w13T_h [(size_t)2*FFD*DD]; // interleaved: even=w1, odd=w3
static __device__ __nv_bfloat16 g_w13T_l [(size_t)2*FFD*DD];
static __device__ __nv_bfloat16 g_w2fT_h [(size_t)DD*FFD];
static __device__ __nv_bfloat16 g_w2fT_l [(size_t)DD*FFD];
static __device__ __nv_bfloat16 g_act_h  [(size_t)TT*FFD];
static __device__ __nv_bfloat16 g_act_l  [(size_t)TT*FFD];
static __device__ __nv_bfloat16 g_qh [(size_t)NHH*TT*DHH];
static __device__ __nv_bfloat16 g_ql [(size_t)NHH*TT*DHH];
static __device__ __nv_bfloat16 g_kh [(size_t)NHH*TT*DHH];
static __device__ __nv_bfloat16 g_kl [(size_t)NHH*TT*DHH];
static __device__ __nv_bfloat16 g_vT_h[(size_t)NHH*DHH*TT];
static __device__ __nv_bfloat16 g_vT_l[(size_t)NHH*DHH*TT];
static __device__ __nv_bfloat16 g_ph [(size_t)NHH*TT*SS];   // also reused as FFN act2_h
static __device__ __nv_bfloat16 g_pl [(size_t)NHH*TT*SS];   // also reused as FFN act2_l

// =================== asm helpers (plain-sm_103-legal) =======================
__device__ __forceinline__ uint32_t smem_u32(const void* p) {
    uint32_t a;
    asm("{ .reg .u64 t; cvta.to.shared.u64 t, %1; cvt.u32.u64 %0, t; }" : "=r"(a) : "l"(p));
    return a;
}
template<int NN> __device__ __forceinline__ void cp_wait() {
    asm volatile("cp.async.wait_group %0;" :: "n"(NN) : "memory");
}
__device__ __forceinline__ void cp_commit() {
    asm volatile("cp.async.commit_group;" ::: "memory");
}
__device__ __forceinline__ void cp16(uint32_t dst, const void* src) {
    asm volatile("cp.async.cg.shared.global [%0], [%1], 16;" :: "r"(dst), "l"(src) : "memory");
}
__device__ __forceinline__ void ldsm4(uint32_t* r, uint32_t addr) {
    asm volatile("ldmatrix.sync.aligned.m8n8.x4.shared.b16 {%0,%1,%2,%3}, [%4];"
                 : "=r"(r[0]), "=r"(r[1]), "=r"(r[2]), "=r"(r[3]) : "r"(addr));
}
__device__ __forceinline__ void mma_bf16(float* c, const uint32_t* a, const uint32_t* b) {
    asm volatile(
        "mma.sync.aligned.m16n8k16.row.col.f32.bf16.bf16.f32 "
        "{%0,%1,%2,%3}, {%4,%5,%6,%7}, {%8,%9}, {%0,%1,%2,%3};"
        : "+f"(c[0]), "+f"(c[1]), "+f"(c[2]), "+f"(c[3])
        : "r"(a[0]), "r"(a[1]), "r"(a[2]), "r"(a[3]), "r"(b[0]), "r"(b[1]));
}
#define SWZ(o) ((o) ^ (((o) >> 3) & 0x30))

__device__ __forceinline__ void split2(float2 v, __nv_bfloat162* hi, __nv_bfloat162* lo) {
    __nv_bfloat16 hx = __float2bfloat16(v.x), hy = __float2bfloat16(v.y);
    hi->x = hx; hi->y = hy;
    lo->x = __float2bfloat16(v.x - __bfloat162float(hx));
    lo->y = __float2bfloat16(v.y - __bfloat162float(hy));
}

// =================== mma.sync split-bf16 GEMM ================================
// MODE 0: plain  MODE 1: causal skip (logits)  MODE 3: GLU epilogue
// MODE 4: 4-way split-K causal PV (fp32 partials; blockIdx.x = quarter)
#define MM_STAGE 32768
#define MM_SMEM  (3 * MM_STAGE)

template<int MODE>
__global__ void __launch_bounds__(256, 2) mma_gemm(
    const __nv_bfloat16* __restrict__ Ahi, const __nv_bfloat16* __restrict__ Alo,
    const __nv_bfloat16* __restrict__ Bhi, const __nv_bfloat16* __restrict__ Blo,
    float* __restrict__ C, const float* __restrict__ R,
    __nv_bfloat16* __restrict__ Chi, __nv_bfloat16* __restrict__ Clo,
    int M, int N, int K, int ldc,
    long long sA, long long sB, long long sC, long long sX)
{
    const int bm = blockIdx.y * 128;
    const int bn = (MODE == 4) ? 0 : blockIdx.x * 128;
    const int kx = (MODE == 4) ? blockIdx.x : 0;
    if (MODE == 1 && bn > bm) return;

    extern __shared__ __align__(1024) char sm[];
    const int tid = threadIdx.x, lane = tid & 31, wid = tid >> 5;
    const int wm = wid & 3, wn = wid >> 2;
    const uint32_t sbase = smem_u32(sm);
    const long long z = blockIdx.z;
    Ahi += z * sA; Alo += z * sA;
    Bhi += z * sB; Blo += z * sB;
    C   += z * sC;
    if (MODE == 4) C += (long long)kx * sX;
    if (R)   R   += z * sC;
    if (Chi) { Chi += z * sC; Clo += z * sC; }

    const __nv_bfloat16* srcs[4] = {Ahi, Alo, Bhi, Blo};
    const int rowbase[4] = {bm, bm, bn, bn};

    auto issue = [&](int kc, int s) {
        #pragma unroll
        for (int i = 0; i < 8; i++) {
            int idx = tid + i * 256;
            int buf = idx >> 9, cc = idx & 511, row = cc >> 2, cb = cc & 3;
            const __nv_bfloat16* src =
                srcs[buf] + (size_t)(rowbase[buf] + row) * K + kc * 32 + cb * 8;
            uint32_t dst = sbase + s * MM_STAGE + buf * 8192 + SWZ(row * 64 + cb * 16);
            cp16(dst, src);
        }
        cp_commit();
    };

    float acc[2][8][4];
    #pragma unroll
    for (int a = 0; a < 2; a++)
        #pragma unroll
        for (int b = 0; b < 8; b++)
            #pragma unroll
            for (int q = 0; q < 4; q++) acc[a][b][q] = 0.f;

    const int Keff = (MODE == 4) ? ((bm + 128 < K) ? bm + 128 : K) : K;
    const int NC = Keff >> 5;
    int cBeg = 0, cEnd = NC;
    if (MODE == 4) {
        const int quart = NC >> 2;     // NC is a multiple of 4
        cBeg = kx * quart;
        cEnd = (kx == 3) ? NC : cBeg + quart;
    }
    issue(cBeg, 0);

    int s = 0;
    for (int c = cBeg; c < cEnd; c++) {
        if (c + 1 < cEnd) { issue(c + 1, (s == 2) ? 0 : s + 1); cp_wait<1>(); }
        else              { cp_wait<0>(); }
        __syncthreads();

        const uint32_t aB = sbase + s * MM_STAGE;
        const uint32_t bB = aB + 16384;
        #pragma unroll
        for (int ks = 0; ks < 2; ks++) {
            uint32_t ah[2][4], al[2][4];
            #pragma unroll
            for (int mt = 0; mt < 2; mt++) {
                int row = wm * 32 + mt * 16 + (lane & 15);
                uint32_t off = SWZ((uint32_t)(row * 64 + ks * 32 + ((lane >> 4) << 4)));
                ldsm4(ah[mt], aB + off);
                ldsm4(al[mt], aB + 8192 + off);
            }
            #pragma unroll
            for (int np = 0; np < 4; np++) {
                int rowb = wn * 64 + np * 16 + (lane & 7) + ((lane >> 4) << 3);
                uint32_t offb = SWZ((uint32_t)(rowb * 64 + ks * 32 + (((lane >> 3) & 1) << 4)));
                uint32_t bh[4], bl[4];
                ldsm4(bh, bB + offb);
                ldsm4(bl, bB + 8192 + offb);
                #pragma unroll
                for (int sub = 0; sub < 2; sub++) {
                    const int nt = np * 2 + sub;
                    #pragma unroll
                    for (int mt = 0; mt < 2; mt++) {
                        mma_bf16(acc[mt][nt], ah[mt], bh + sub * 2);
                        mma_bf16(acc[mt][nt], ah[mt], bl + sub * 2);
                        mma_bf16(acc[mt][nt], al[mt], bh + sub * 2);
                    }
                }
            }
        }
        s = (s == 2) ? 0 : s + 1;
    }

    #pragma unroll
    for (int mt = 0; mt < 2; mt++) {
        int r0 = bm + wm * 32 + mt * 16 + (lane >> 2);
        #pragma unroll
        for (int nt = 0; nt < 8; nt++) {
            if (MODE == 3) {
                int f = (bn >> 1) + wn * 32 + nt * 4 + (lane & 3);
                float a0 = acc[mt][nt][0], b0 = acc[mt][nt][1];
                float a1 = acc[mt][nt][2], b1 = acc[mt][nt][3];
                float v0 = (a0 / (1.f + __expf(-a0))) * b0;
                float v1 = (a1 / (1.f + __expf(-a1))) * b1;
                size_t i0 = (size_t)r0 * ldc + f;
                size_t i1 = i0 + 8 * (size_t)ldc;
                __nv_bfloat16 h0 = __float2bfloat16(v0);
                __nv_bfloat16 h1 = __float2bfloat16(v1);
                Chi[i0] = h0; Clo[i0] = __float2bfloat16(v0 - __bfloat162float(h0));
                Chi[i1] = h1; Clo[i1] = __float2bfloat16(v1 - __bfloat162float(h1));
                continue;
            }
            int col = bn + wn * 64 + nt * 8 + (lane & 3) * 2;
            size_t i0 = (size_t)r0 * ldc + col;
            size_t i1 = i0 + 8 * (size_t)ldc;
            float2 v0 = {acc[mt][nt][0], acc[mt][nt][1]};
            float2 v1 = {acc[mt][nt][2], acc[mt][nt][3]};
            if (MODE != 4 && Chi) {
                __nv_bfloat162 h0, l0, h1, l1;
                split2(v0, &h0, &l0);
                split2(v1, &h1, &l1);
                *(__nv_bfloat162*)(Chi + i0) = h0;
                *(__nv_bfloat162*)(Clo + i0) = l0;
                *(__nv_bfloat162*)(Chi + i1) = h1;
                *(__nv_bfloat162*)(Clo + i1) = l1;
            } else {
                if (R) {
                    float2 a = *(const float2*)(R + i0);
                    float2 b = *(const float2*)(R + i1);
                    v0.x += a.x; v0.y += a.y; v1.x += b.x; v1.y += b.y;
                }
                *(float2*)(C + i0) = v0;
                *(float2*)(C + i1) = v1;
            }
        }
    }
}

// PV split-K combine: act[t][h*128+d] = split(P0+P1+P2+P3)
__global__ void pv_combine(const float* __restrict__ P,
                           __nv_bfloat16* __restrict__ hi, __nv_bfloat16* __restrict__ lo)
{
    long long i = (long long)blockIdx.x * 256 + threadIdx.x;
    const long long TOT = (long long)NHH * TT * DHH;
    if (i < TOT) {
        float v = P[i] + P[i + TOT] + P[i + 2 * TOT] + P[i + 3 * TOT];
        long long h = i / ((long long)TT * DHH);
        long long r = i - h * (long long)TT * DHH;
        long long t = r / DHH, d = r - t * DHH;
        size_t o = (size_t)t * DD + h * DHH + d;
        __nv_bfloat16 hv = __float2bfloat16(v);
        hi[o] = hv;
        lo[o] = __float2bfloat16(v - __bfloat162float(hv));
    }
}

// =================== conversion kernels =====================================
__global__ void convT(const float* __restrict__ W, __nv_bfloat16* __restrict__ hi,
                      __nv_bfloat16* __restrict__ lo, int K, int N,
                      long long sW, long long sO, int rmul, int radd)
{
    W  += (long long)blockIdx.z * sW;
    hi += (long long)blockIdx.z * sO;
    lo += (long long)blockIdx.z * sO;
    __shared__ float t[32][33];
    int n0 = blockIdx.x * 32, k0 = blockIdx.y * 32;
    int x = threadIdx.x, y = threadIdx.y;
    #pragma unroll
    for (int yy = y; yy < 32; yy += 8)
        t[yy][x] = W[(size_t)(k0 + yy) * N + n0 + x];
    __syncthreads();
    #pragma unroll
    for (int yy = y; yy < 32; yy += 8) {
        float v = t[x][yy];
        __nv_bfloat16 h = __float2bfloat16(v);
        size_t o = ((size_t)(n0 + yy) * rmul + radd) * K + k0 + x;
        hi[o] = h;
        lo[o] = __float2bfloat16(v - __bfloat162float(h));
    }
}

// =================== fused SIMT kernels =====================================
__global__ void rmsnorm_split(const float* __restrict__ x, const float* __restrict__ w,
                              __nv_bfloat16* __restrict__ hi, __nv_bfloat16* __restrict__ lo,
                              int d)
{
    long long t = blockIdx.x;
    const float* r = x + t * (long long)d;
    int tid = threadIdx.x;
    float ss = 0.f;
    for (int i = tid; i < d; i += blockDim.x) { float v = r[i]; ss += v * v; }
    for (int off = 16; off > 0; off >>= 1) ss += __shfl_xor_sync(0xffffffffu, ss, off);
    __shared__ float sh[8];
    if ((tid & 31) == 0) sh[tid >> 5] = ss;
    __syncthreads();
    float tot = 0.f;
    #pragma unroll
    for (int i = 0; i < 8; i++) tot += sh[i];
    float inv = rsqrtf(tot / d + 1e-6f);
    for (int i = tid; i < d; i += blockDim.x) {
        float v = r[i] * inv * w[i];
        __nv_bfloat16 h = __float2bfloat16(v);
        hi[t * (long long)d + i] = h;
        lo[t * (long long)d + i] = __float2bfloat16(v - __bfloat162float(h));
    }
}

// qkv split + head rmsnorm + rope; reads fused qkv|dwh|ddv rows (stride QKD)
__global__ void qkv_prep(const float* __restrict__ qkv,
                         const float* __restrict__ qw, const float* __restrict__ kw,
                         __nv_bfloat16* __restrict__ qh, __nv_bfloat16* __restrict__ ql,
                         __nv_bfloat16* __restrict__ kh, __nv_bfloat16* __restrict__ kl,
                         float* __restrict__ v)
{
    int n = blockIdx.x, t = blockIdx.y, d = threadIdx.x;
    const float* rowp = qkv + (long long)t * QKD + n * DHH;
    float qv = rowp[d], kv = rowp[DD + d], vv = rowp[2 * DD + d];

    float sq = qv * qv, sk = kv * kv;
    for (int off = 16; off > 0; off >>= 1) {
        sq += __shfl_xor_sync(0xffffffffu, sq, off);
        sk += __shfl_xor_sync(0xffffffffu, sk, off);
    }
    __shared__ float rq[4], rk[4];
    if ((d & 31) == 0) { rq[d >> 5] = sq; rk[d >> 5] = sk; }
    __syncthreads();
    float vq = (rq[0] + rq[1] + rq[2] + rq[3]) / (float)DHH;
    float vk = (rk[0] + rk[1] + rk[2] + rk[3]) / (float)DHH;
    float qn = qv * rsqrtf(vq + 1e-6f) * qw[d];
    float kn = kv * rsqrtf(vk + 1e-6f) * kw[d];

    __shared__ float sqb[DHH], skb[DHH];
    sqb[d] = qn; skb[d] = kn;
    __syncthreads();

    long long base = ((long long)n * TT + t) * DHH;
    v[base + d] = vv;
    if (d < 64) {
        float inv = powf(10000.f, -((float)d) / 64.f);
        float ang = (float)t * inv;
        float c, s;
        sincosf(ang, &s, &c);
        float q1 = sqb[d], q2 = sqb[64 + d];
        float k1 = skb[d], k2 = skb[64 + d];
        const float sc = 0.08838834764831845f;
        float qo0 = (q1 * c - q2 * s) * sc, qo1 = (q2 * c + q1 * s) * sc;
        float ko0 = (k1 * c - k2 * s),      ko1 = (k2 * c + k1 * s);
        __nv_bfloat16 h;
        h = __float2bfloat16(qo0); qh[base + 2*d]   = h; ql[base + 2*d]   = __float2bfloat16(qo0 - __bfloat162float(h));
        h = __float2bfloat16(qo1); qh[base + 2*d+1] = h; ql[base + 2*d+1] = __float2bfloat16(qo1 - __bfloat162float(h));
        h = __float2bfloat16(ko0); kh[base + 2*d]   = h; kl[base + 2*d]   = __float2bfloat16(ko0 - __bfloat162float(h));
        h = __float2bfloat16(ko1); kh[base + 2*d+1] = h; kl[base + 2*d+1] = __float2bfloat16(ko1 - __bfloat162float(h));
    }
}

// w projection; reads RAW dwh (pre-gelu) at qkvb cols [6144,6400), stride QKD
__global__ void wproj_k(const float* __restrict__ dwh_raw, const float* __restrict__ qkw,
                        float* __restrict__ w)
{
    int t = blockIdx.x;
    int tid = threadIdx.x;
    __shared__ float sh[256];
    {
        float xg = dwh_raw[(long long)t * QKD + tid];
        sh[tid] = 0.5f * xg * (1.f + erff(xg * 0.7071067811865475f));
    }
    __syncthreads();
    int c = tid >> 6, r = tid & 63, i = r >> 4, n = r & 15;
    float acc = 0.f;
    #pragma unroll 8
    for (int kk = 0; kk < 64; kk++)
        acc += sh[c * 64 + kk] * qkw[((c * 64 + kk) * 4 + i) * 16 + n];
    __shared__ float sw[256];
    sw[tid] = acc;
    __syncthreads();
    float out = acc;
    if (i < 2) {
        float ss = 0.f;
        #pragma unroll
        for (int m = 0; m < 16; m++) { float vv = sw[c * 64 + i * 16 + m]; ss += vv * vv; }
        out = acc * rsqrtf(ss / 16.f + 1e-6f);
    }
    w[(long long)t * 256 + tid] = out;
}

// cross_head_proj. POST=0: in-place on X, lower-triangle tiles.
// POST=1: writes bf16 split ph/pl, tiles covering s < 128-block edge of t.
template<int POST>
__global__ void crosshead_k(float* __restrict__ X, const float* __restrict__ W,
                            const float* __restrict__ ddv_raw,
                            int cq, int ck, int qoff, int koff,
                            __nv_bfloat16* __restrict__ ph, __nv_bfloat16* __restrict__ pl)
{
    if (POST == 0) { if (blockIdx.x > blockIdx.y) return; }
    else           { if ((blockIdx.x >> 2) > (blockIdx.y >> 2)) return; }
    __shared__ float q1[32][2][16], q2[32][2][16], qd[32][16];
    __shared__ float k1[32][2][16], k2[32][2][16], kd[32][16];
    int s0 = blockIdx.x * 32, t0 = blockIdx.y * 32;
    int tid = threadIdx.x;

    for (int idx = tid; idx < 32 * 64; idx += 256) {
        int row = idx >> 6, r = idx & 63;
        int i = r >> 4, n = r & 15;
        float vq = W[(long long)(t0 + row) * 256 + cq * 64 + i * 16 + n];
        float vk = W[(long long)(s0 + row) * 256 + ck * 64 + i * 16 + n];
        if (i < 2) { q1[row][i][n] = vq; k1[row][i][n] = vk; }
        else       { q2[row][i - 2][n] = vq; k2[row][i - 2][n] = vk; }
    }
    for (int idx = tid; idx < 32 * 16; idx += 256) {
        int row = idx >> 4, n = idx & 15;
        qd[row][n] = tanhf(ddv_raw[(long long)(t0 + row) * QKD + qoff + n]);
        kd[row][n] = tanhf(ddv_raw[(long long)(s0 + row) * QKD + koff + n]);
    }
    __syncthreads();

    const long long TSs = (long long)TT * SS;
    int si = tid & 31;
    int s = s0 + si;
    for (int tt = (tid >> 5); tt < 32; tt += 8) {
        long long base = (long long)(t0 + tt) * SS + s;
        float xv[16];
        #pragma unroll
        for (int n = 0; n < 16; n++) xv[n] = X[n * TSs + base];
        float a0 = 0.f, a1 = 0.f, b0 = 0.f, b1 = 0.f;
        #pragma unroll
        for (int n = 0; n < 16; n++) {
            a0 += xv[n] * q1[tt][0][n];
            a1 += xv[n] * q1[tt][1][n];
            b0 += xv[n] * k1[si][0][n];
            b1 += xv[n] * k1[si][1][n];
        }
        #pragma unroll
        for (int n = 0; n < 16; n++) {
            float ov = xv[n] * (1.f + qd[tt][n] + kd[si][n])
                     + a0 * q2[tt][0][n] + a1 * q2[tt][1][n]
                     + b0 * k2[si][0][n] + b1 * k2[si][1][n];
            if (POST == 0) {
                X[n * TSs + base] = ov;
            } else {
                __nv_bfloat16 h = __float2bfloat16(ov);
                ph[n * TSs + base] = h;
                pl[n * TSs + base] = __float2bfloat16(ov - __bfloat162float(h));
            }
        }
    }
}

// causal softmax with smem exp cache
__global__ void softmax_causal(float* __restrict__ X)
{
    __shared__ float ex[SS];
    int t = blockIdx.x, n = blockIdx.y;
    float* row = X + ((long long)n * TT + t) * (long long)SS;
    int valid = t + 1;
    int lim = ((t >> 7) + 1) << 7;
    int tid = threadIdx.x;
    __shared__ float sh[8];
    __shared__ float bcast;

    float m = -3.4e38f;
    for (int s = tid; s < valid; s += 256) m = fmaxf(m, row[s]);
    for (int off = 16; off > 0; off >>= 1) m = fmaxf(m, __shfl_xor_sync(0xffffffffu, m, off));
    if ((tid & 31) == 0) sh[tid >> 5] = m;
    __syncthreads();
    float mm = sh[0];
    #pragma unroll
    for (int i = 1; i < 8; i++) mm = fmaxf(mm, sh[i]);
    __syncthreads();

    float sum = 0.f;
    for (int s = tid; s < valid; s += 256) {
        float e = __expf(row[s] - mm);
        ex[s] = e;
        sum += e;
    }
    for (int off = 16; off > 0; off >>= 1) sum += __shfl_xor_sync(0xffffffffu, sum, off);
    if ((tid & 31) == 0) sh[tid >> 5] = sum;
    __syncthreads();
    if (tid == 0) {
        float tot = 0.f;
        #pragma unroll
        for (int i = 0; i < 8; i++) tot += sh[i];
        bcast = 1.f / tot;
    }
    __syncthreads();
    float inv = bcast;
    for (int s = tid; s < lim; s += 256)
        row[s] = (s < valid) ? ex[s] * inv : 0.f;
}

// =================== host orchestration =====================================
extern "C" void kernel_launch(void* const* d_in, const int* in_sizes, int n_in,
                              void* d_out, int out_size)
{
    const float* x       = (const float*)d_in[0];
    const float* attn_nw = (const float*)d_in[1];
    const float* wqkv    = (const float*)d_in[2];
    const float* q_nw    = (const float*)d_in[3];
    const float* k_nw    = (const float*)d_in[4];
    const float* dw1     = (const float*)d_in[5];
    const float* qkw     = (const float*)d_in[6];
    const float* dd      = (const float*)d_in[7];
    const float* wo      = (const float*)d_in[8];
    const float* ffn_nw  = (const float*)d_in[9];
    const float* w1f     = (const float*)d_in[10];
    const float* w3f     = (const float*)d_in[11];
    const float* w2f     = (const float*)d_in[12];
    float* out = (float*)d_out;

    static float *qkvb = nullptr, *v, *lg, *w, *h;
    static __nv_bfloat16 *wallT_h, *wallT_l, *woT_h, *woT_l, *w13T_h, *w13T_l,
                         *w2fT_h, *w2fT_l, *act_h, *act_l,
                         *qh, *ql, *kh, *kl, *vT_h, *vT_l, *ph, *pl;
    if (!qkvb) {
        cudaGetSymbolAddress((void**)&qkvb, g_qkv);
        cudaGetSymbolAddress((void**)&v,    g_v);
        cudaGetSymbolAddress((void**)&lg,   g_lg);
        cudaGetSymbolAddress((void**)&w,    g_w);
        cudaGetSymbolAddress((void**)&h,    g_h);
        cudaGetSymbolAddress((void**)&wallT_h, g_wallT_h);
        cudaGetSymbolAddress((void**)&wallT_l, g_wallT_l);
        cudaGetSymbolAddress((void**)&woT_h,   g_woT_h);
        cudaGetSymbolAddress((void**)&woT_l,   g_woT_l);
        cudaGetSymbolAddress((void**)&w13T_h,  g_w13T_h);
        cudaGetSymbolAddress((void**)&w13T_l,  g_w13T_l);
        cudaGetSymbolAddress((void**)&w2fT_h,  g_w2fT_h);
        cudaGetSymbolAddress((void**)&w2fT_l,  g_w2fT_l);
        cudaGetSymbolAddress((void**)&act_h,   g_act_h);
        cudaGetSymbolAddress((void**)&act_l,   g_act_l);
        cudaGetSymbolAddress((void**)&qh,   g_qh);
        cudaGetSymbolAddress((void**)&ql,   g_ql);
        cudaGetSymbolAddress((void**)&kh,   g_kh);
        cudaGetSymbolAddress((void**)&kl,   g_kl);
        cudaGetSymbolAddress((void**)&vT_h, g_vT_h);
        cudaGetSymbolAddress((void**)&vT_l, g_vT_l);
        cudaGetSymbolAddress((void**)&ph,   g_ph);
        cudaGetSymbolAddress((void**)&pl,   g_pl);
        cudaFuncSetAttribute(mma_gemm<0>, cudaFuncAttributeMaxDynamicSharedMemorySize, MM_SMEM);
        cudaFuncSetAttribute(mma_gemm<1>, cudaFuncAttributeMaxDynamicSharedMemorySize, MM_SMEM);
        cudaFuncSetAttribute(mma_gemm<3>, cudaFuncAttributeMaxDynamicSharedMemorySize, MM_SMEM);
        cudaFuncSetAttribute(mma_gemm<4>, cudaFuncAttributeMaxDynamicSharedMemorySize, MM_SMEM);
    }

    dim3 tb(32, 8);
    // weight conversions (w1f -> even rows, w3f -> odd rows of w13T)
    convT<<<dim3(3 * DD / 32, DD / 32), tb>>>(wqkv, wallT_h, wallT_l, DD, 3 * DD, 0, 0, 1, 0);
    convT<<<dim3(256 / 32, DD / 32), tb>>>(dw1, wallT_h + (size_t)3 * DD * DD,
                                           wallT_l + (size_t)3 * DD * DD, DD, 256, 0, 0, 1, 0);
    convT<<<dim3(64 / 32, DD / 32), tb>>>(dd, wallT_h + (size_t)(3 * DD + 256) * DD,
                                          wallT_l + (size_t)(3 * DD + 256) * DD, DD, 64, 0, 0, 1, 0);
    convT<<<dim3(DD / 32, DD / 32), tb>>>(wo,  woT_h,  woT_l,  DD, DD, 0, 0, 1, 0);
    convT<<<dim3(FFD / 32, DD / 32), tb>>>(w1f, w13T_h, w13T_l, DD, FFD, 0, 0, 2, 0);
    convT<<<dim3(FFD / 32, DD / 32), tb>>>(w3f, w13T_h, w13T_l, DD, FFD, 0, 0, 2, 1);
    convT<<<dim3(DD / 32, FFD / 32), tb>>>(w2f, w2fT_h, w2fT_l, FFD, DD, 0, 0, 1, 0);

    // 1. hn = rmsnorm(x) -> split act
    rmsnorm_split<<<TT, 256>>>(x, attn_nw, act_h, act_l, DD);
    // 2. [qkv | dwh | ddv] = hn @ [wqkv | dw1 | dd]   (one merged GEMM)
    mma_gemm<0><<<dim3(QKD / 128, TT / 128), 256, MM_SMEM>>>(
        act_h, act_l, wallT_h, wallT_l, qkvb, nullptr, nullptr, nullptr,
        TT, QKD, DD, QKD, 0, 0, 0, 0);
    // 3. split + head rmsnorm + rope ; v fp32 then transpose-split
    qkv_prep<<<dim3(NHH, TT), 128>>>(qkvb, q_nw, k_nw, qh, ql, kh, kl, v);
    convT<<<dim3(DHH / 32, TT / 32, NHH), tb>>>(v, vT_h, vT_l, TT, DHH,
        (long long)TT * DHH, (long long)DHH * TT, 1, 0);
    // 4. dyn weights: gelu fused into wproj; tanh fused into crosshead loads
    wproj_k<<<TT, 256>>>(qkvb + 3 * DD, qkw, w);
    // 5. logits = q @ k^T (causal tiles only)
    mma_gemm<1><<<dim3(TT / 128, TT / 128, NHH), 256, MM_SMEM>>>(
        qh, ql, kh, kl, lg, nullptr, nullptr, nullptr, TT, TT, DHH, SS,
        (long long)TT * DHH, (long long)TT * DHH, (long long)TT * SS, 0);
    // 6-8. cross_head pre, softmax (smem exp cache), cross_head post -> ph/pl
    crosshead_k<0><<<dim3(SS / 32, TT / 32), 256>>>(
        lg, w, qkvb + 3 * DD + 256, 0, 1, 0, 16, nullptr, nullptr);
    softmax_causal<<<dim3(TT, NHH), 256>>>(lg);
    crosshead_k<1><<<dim3(SS / 32, TT / 32), 256>>>(
        lg, w, qkvb + 3 * DD + 256, 2, 3, 32, 48, ph, pl);
    // 9. o = probs @ v, 4-way split-K (fp32 partials into dead lg), then combine
    mma_gemm<4><<<dim3(4, TT / 128, NHH), 256, MM_SMEM>>>(
        ph, pl, vT_h, vT_l, lg, nullptr, nullptr, nullptr, TT, DHH, TT, DHH,
        (long long)TT * SS, (long long)DHH * TT, (long long)TT * DHH,
        (long long)NHH * TT * DHH);
    pv_combine<<<(int)(((long long)NHH * TT * DHH + 255) / 256), 256>>>(lg, act_h, act_l);
    // 10. h = x + o @ wo
    mma_gemm<0><<<dim3(DD / 128, TT / 128), 256, MM_SMEM>>>(
        act_h, act_l, woT_h, woT_l, h, x, nullptr, nullptr, TT, DD, DD, DD, 0, 0, 0, 0);
    // 11. ffn: rmsnorm->split(act), interleaved w1|w3 gemm + fused swiglu
    //     -> split act2 (ph/pl scratch, DISJOINT from A), then w2 gemm
    rmsnorm_split<<<TT, 256>>>(h, ffn_nw, act_h, act_l, DD);
    mma_gemm<3><<<dim3(2 * FFD / 128, TT / 128), 256, MM_SMEM>>>(
        act_h, act_l, w13T_h, w13T_l, nullptr, nullptr, ph, pl,
        TT, 2 * FFD, DD, FFD, 0, 0, 0, 0);
    mma_gemm<0><<<dim3(DD / 128, TT / 128), 256, MM_SMEM>>>(
        ph, pl, w2fT_h, w2fT_l, out, h, nullptr, nullptr, TT, DD, FFD, DD, 0, 0, 0, 0);
}

// round 15
// speedup vs baseline: 1.1298x; 1.0331x over previous
#include <cuda_runtime.h>
#include <cuda_bf16.h>
#include <math.h>
#include <stdint.h>

#define TT   2048
#define DD   2048
#define NHH  16
#define DHH  128
#define FFD  5632
#define SS   TT
#define QKD  6528   // 3*DD + 256 + 128 (qkv | dw1-hidden | dd)

// ---------------- scratch (static device globals; no allocation) ----------
static __device__ float g_qkv[(size_t)TT*QKD];   // qkv | dwh(raw) | ddv(raw)
static __device__ float g_v  [(size_t)NHH*TT*DHH];
static __device__ float g_lg [(size_t)NHH*TT*SS];   // logits; later PV split-K partials
static __device__ float g_w  [(size_t)TT*256];
static __device__ float g_h  [(size_t)TT*DD];

// bf16 split operands
static __device__ __nv_bfloat16 g_wallT_h[(size_t)QKD*DD];  // rows 6464..6527 stay zero
static __device__ __nv_bfloat16 g_wallT_l[(size_t)QKD*DD];
static __device__ __nv_bfloat16 g_woT_h  [(size_t)DD*DD];
static __device__ __nv_bfloat16 g_woT_l  [(size_t)DD*DD];
static __device__ __nv_bfloat16 g_w13T_h [(size_t)2*FFD*DD]; // interleaved: even=w1, odd=w3
static __device__ __nv_bfloat16 g_w13T_l [(size_t)2*FFD*DD];
static __device__ __nv_bfloat16 g_w2fT_h [(size_t)DD*FFD];
static __device__ __nv_bfloat16 g_w2fT_l [(size_t)DD*FFD];
static __device__ __nv_bfloat16 g_act_h  [(size_t)TT*FFD];
static __device__ __nv_bfloat16 g_act_l  [(size_t)TT*FFD];
static __device__ __nv_bfloat16 g_qh [(size_t)NHH*TT*DHH];
static __device__ __nv_bfloat16 g_ql [(size_t)NHH*TT*DHH];
static __device__ __nv_bfloat16 g_kh [(size_t)NHH*TT*DHH];
static __device__ __nv_bfloat16 g_kl [(size_t)NHH*TT*DHH];
static __device__ __nv_bfloat16 g_vT_h[(size_t)NHH*DHH*TT];
static __device__ __nv_bfloat16 g_vT_l[(size_t)NHH*DHH*TT];
static __device__ __nv_bfloat16 g_ph [(size_t)NHH*TT*SS];   // also reused as FFN act2_h
static __device__ __nv_bfloat16 g_pl [(size_t)NHH*TT*SS];   // also reused as FFN act2_l

// =================== asm helpers (plain-sm_103-legal) =======================
__device__ __forceinline__ uint32_t smem_u32(const void* p) {
    uint32_t a;
    asm("{ .reg .u64 t; cvta.to.shared.u64 t, %1; cvt.u32.u64 %0, t; }" : "=r"(a) : "l"(p));
    return a;
}
template<int NN> __device__ __forceinline__ void cp_wait() {
    asm volatile("cp.async.wait_group %0;" :: "n"(NN) : "memory");
}
__device__ __forceinline__ void cp_commit() {
    asm volatile("cp.async.commit_group;" ::: "memory");
}
__device__ __forceinline__ void cp16(uint32_t dst, const void* src) {
    asm volatile("cp.async.cg.shared.global [%0], [%1], 16;" :: "r"(dst), "l"(src) : "memory");
}
__device__ __forceinline__ void ldsm4(uint32_t* r, uint32_t addr) {
    asm volatile("ldmatrix.sync.aligned.m8n8.x4.shared.b16 {%0,%1,%2,%3}, [%4];"
                 : "=r"(r[0]), "=r"(r[1]), "=r"(r[2]), "=r"(r[3]) : "r"(addr));
}
__device__ __forceinline__ void mma_bf16(float* c, const uint32_t* a, const uint32_t* b) {
    asm volatile(
        "mma.sync.aligned.m16n8k16.row.col.f32.bf16.bf16.f32 "
        "{%0,%1,%2,%3}, {%4,%5,%6,%7}, {%8,%9}, {%0,%1,%2,%3};"
        : "+f"(c[0]), "+f"(c[1]), "+f"(c[2]), "+f"(c[3])
        : "r"(a[0]), "r"(a[1]), "r"(a[2]), "r"(a[3]), "r"(b[0]), "r"(b[1]));
}
#define SWZ(o) ((o) ^ (((o) >> 3) & 0x30))

__device__ __forceinline__ void split2(float2 v, __nv_bfloat162* hi, __nv_bfloat162* lo) {
    __nv_bfloat16 hx = __float2bfloat16(v.x), hy = __float2bfloat16(v.y);
    hi->x = hx; hi->y = hy;
    lo->x = __float2bfloat16(v.x - __bfloat162float(hx));
    lo->y = __float2bfloat16(v.y - __bfloat162float(hy));
}

// =================== mma.sync split-bf16 GEMM ================================
// MODE 0: plain  MODE 1: causal skip (logits)  MODE 3: GLU epilogue
// MODE 4: 4-way split-K causal PV (fp32 partials; blockIdx.x = quarter)
#define MM_STAGE 32768
#define MM_SMEM  (3 * MM_STAGE)

template<int MODE>
__global__ void __launch_bounds__(256, 2) mma_gemm(
    const __nv_bfloat16* __restrict__ Ahi, const __nv_bfloat16* __restrict__ Alo,
    const __nv_bfloat16* __restrict__ Bhi, const __nv_bfloat16* __restrict__ Blo,
    float* __restrict__ C, const float* __restrict__ R,
    __nv_bfloat16* __restrict__ Chi, __nv_bfloat16* __restrict__ Clo,
    int M, int N, int K, int ldc,
    long long sA, long long sB, long long sC, long long sX)
{
    const int bm = blockIdx.y * 128;
    const int bn = (MODE == 4) ? 0 : blockIdx.x * 128;
    const int kx = (MODE == 4) ? blockIdx.x : 0;
    if (MODE == 1 && bn > bm) return;

    extern __shared__ __align__(1024) char sm[];
    const int tid = threadIdx.x, lane = tid & 31, wid = tid >> 5;
    const int wm = wid & 3, wn = wid >> 2;
    const uint32_t sbase = smem_u32(sm);
    const long long z = blockIdx.z;
    Ahi += z * sA; Alo += z * sA;
    Bhi += z * sB; Blo += z * sB;
    C   += z * sC;
    if (MODE == 4) C += (long long)kx * sX;
    if (R)   R   += z * sC;
    if (Chi) { Chi += z * sC; Clo += z * sC; }

    const __nv_bfloat16* srcs[4] = {Ahi, Alo, Bhi, Blo};
    const int rowbase[4] = {bm, bm, bn, bn};

    auto issue = [&](int kc, int s) {
        #pragma unroll
        for (int i = 0; i < 8; i++) {
            int idx = tid + i * 256;
            int buf = idx >> 9, cc = idx & 511, row = cc >> 2, cb = cc & 3;
            const __nv_bfloat16* src =
                srcs[buf] + (size_t)(rowbase[buf] + row) * K + kc * 32 + cb * 8;
            uint32_t dst = sbase + s * MM_STAGE + buf * 8192 + SWZ(row * 64 + cb * 16);
            cp16(dst, src);
        }
        cp_commit();
    };

    float acc[2][8][4];
    #pragma unroll
    for (int a = 0; a < 2; a++)
        #pragma unroll
        for (int b = 0; b < 8; b++)
            #pragma unroll
            for (int q = 0; q < 4; q++) acc[a][b][q] = 0.f;

    const int Keff = (MODE == 4) ? ((bm + 128 < K) ? bm + 128 : K) : K;
    const int NC = Keff >> 5;
    int cBeg = 0, cEnd = NC;
    if (MODE == 4) {
        const int quart = NC >> 2;     // NC is a multiple of 4
        cBeg = kx * quart;
        cEnd = (kx == 3) ? NC : cBeg + quart;
    }
    issue(cBeg, 0);

    int s = 0;
    for (int c = cBeg; c < cEnd; c++) {
        if (c + 1 < cEnd) { issue(c + 1, (s == 2) ? 0 : s + 1); cp_wait<1>(); }
        else              { cp_wait<0>(); }
        __syncthreads();

        const uint32_t aB = sbase + s * MM_STAGE;
        const uint32_t bB = aB + 16384;
        #pragma unroll
        for (int ks = 0; ks < 2; ks++) {
            uint32_t ah[2][4], al[2][4];
            #pragma unroll
            for (int mt = 0; mt < 2; mt++) {
                int row = wm * 32 + mt * 16 + (lane & 15);
                uint32_t off = SWZ((uint32_t)(row * 64 + ks * 32 + ((lane >> 4) << 4)));
                ldsm4(ah[mt], aB + off);
                ldsm4(al[mt], aB + 8192 + off);
            }
            #pragma unroll
            for (int np = 0; np < 4; np++) {
                int rowb = wn * 64 + np * 16 + (lane & 7) + ((lane >> 4) << 3);
                uint32_t offb = SWZ((uint32_t)(rowb * 64 + ks * 32 + (((lane >> 3) & 1) << 4)));
                uint32_t bh[4], bl[4];
                ldsm4(bh, bB + offb);
                ldsm4(bl, bB + 8192 + offb);
                #pragma unroll
                for (int sub = 0; sub < 2; sub++) {
                    const int nt = np * 2 + sub;
                    #pragma unroll
                    for (int mt = 0; mt < 2; mt++) {
                        mma_bf16(acc[mt][nt], ah[mt], bh + sub * 2);
                        mma_bf16(acc[mt][nt], ah[mt], bl + sub * 2);
                        mma_bf16(acc[mt][nt], al[mt], bh + sub * 2);
                    }
                }
            }
        }
        s = (s == 2) ? 0 : s + 1;
    }

    #pragma unroll
    for (int mt = 0; mt < 2; mt++) {
        int r0 = bm + wm * 32 + mt * 16 + (lane >> 2);
        #pragma unroll
        for (int nt = 0; nt < 8; nt++) {
            if (MODE == 3) {
                int f = (bn >> 1) + wn * 32 + nt * 4 + (lane & 3);
                float a0 = acc[mt][nt][0], b0 = acc[mt][nt][1];
                float a1 = acc[mt][nt][2], b1 = acc[mt][nt][3];
                float v0 = (a0 / (1.f + __expf(-a0))) * b0;
                float v1 = (a1 / (1.f + __expf(-a1))) * b1;
                size_t i0 = (size_t)r0 * ldc + f;
                size_t i1 = i0 + 8 * (size_t)ldc;
                __nv_bfloat16 h0 = __float2bfloat16(v0);
                __nv_bfloat16 h1 = __float2bfloat16(v1);
                Chi[i0] = h0; Clo[i0] = __float2bfloat16(v0 - __bfloat162float(h0));
                Chi[i1] = h1; Clo[i1] = __float2bfloat16(v1 - __bfloat162float(h1));
                continue;
            }
            int col = bn + wn * 64 + nt * 8 + (lane & 3) * 2;
            size_t i0 = (size_t)r0 * ldc + col;
            size_t i1 = i0 + 8 * (size_t)ldc;
            float2 v0 = {acc[mt][nt][0], acc[mt][nt][1]};
            float2 v1 = {acc[mt][nt][2], acc[mt][nt][3]};
            if (MODE != 4 && Chi) {
                __nv_bfloat162 h0, l0, h1, l1;
                split2(v0, &h0, &l0);
                split2(v1, &h1, &l1);
                *(__nv_bfloat162*)(Chi + i0) = h0;
                *(__nv_bfloat162*)(Clo + i0) = l0;
                *(__nv_bfloat162*)(Chi + i1) = h1;
                *(__nv_bfloat162*)(Clo + i1) = l1;
            } else {
                if (R) {
                    float2 a = *(const float2*)(R + i0);
                    float2 b = *(const float2*)(R + i1);
                    v0.x += a.x; v0.y += a.y; v1.x += b.x; v1.y += b.y;
                }
                *(float2*)(C + i0) = v0;
                *(float2*)(C + i1) = v1;
            }
        }
    }
}

// PV split-K combine: act[t][h*128+d] = split(P0+P1+P2+P3)
__global__ void pv_combine(const float* __restrict__ P,
                           __nv_bfloat16* __restrict__ hi, __nv_bfloat16* __restrict__ lo)
{
    long long i = (long long)blockIdx.x * 256 + threadIdx.x;
    const long long TOT = (long long)NHH * TT * DHH;
    if (i < TOT) {
        float v = P[i] + P[i + TOT] + P[i + 2 * TOT] + P[i + 3 * TOT];
        long long h = i / ((long long)TT * DHH);
        long long r = i - h * (long long)TT * DHH;
        long long t = r / DHH, d = r - t * DHH;
        size_t o = (size_t)t * DD + h * DHH + d;
        __nv_bfloat16 hv = __float2bfloat16(v);
        hi[o] = hv;
        lo[o] = __float2bfloat16(v - __bfloat162float(hv));
    }
}

// =================== conversion kernels =====================================
// W[K][N] fp32 -> hi/lo[(N*rmul+radd)][K] bf16 (batched over z).
// 64x64 tile, 256 threads: float4-vectorized loads, 128B-coalesced bf162 stores.
__global__ void convT(const float* __restrict__ W, __nv_bfloat16* __restrict__ hi,
                      __nv_bfloat16* __restrict__ lo, int K, int N,
                      long long sW, long long sO, int rmul, int radd)
{
    W  += (long long)blockIdx.z * sW;
    hi += (long long)blockIdx.z * sO;
    lo += (long long)blockIdx.z * sO;
    __shared__ float t[64][65];
    int n0 = blockIdx.x * 64, k0 = blockIdx.y * 64;
    int tid = threadIdx.x;

    // load 64 k-rows x 64 n-cols, float4 per thread x4
    #pragma unroll
    for (int i = 0; i < 4; i++) {
        int idx = tid + i * 256;              // 0..1023
        int row = idx >> 4, c4 = idx & 15;    // row 0..63, c4 0..15
        float4 v = *reinterpret_cast<const float4*>(
            W + (size_t)(k0 + row) * N + n0 + c4 * 4);
        t[row][c4 * 4 + 0] = v.x;
        t[row][c4 * 4 + 1] = v.y;
        t[row][c4 * 4 + 2] = v.z;
        t[row][c4 * 4 + 3] = v.w;
    }
    __syncthreads();

    // store 64 n-rows x 64 k-cols as bf162 pairs (128B contiguous per n-row)
    #pragma unroll
    for (int i = 0; i < 8; i++) {
        int idx = tid + i * 256;              // 0..2047
        int nr = idx >> 5, c2 = idx & 31;     // nr 0..63, c2 0..31
        float v0 = t[c2 * 2][nr];
        float v1 = t[c2 * 2 + 1][nr];
        __nv_bfloat16 h0 = __float2bfloat16(v0);
        __nv_bfloat16 h1 = __float2bfloat16(v1);
        __nv_bfloat162 hv, lv;
        hv.x = h0; hv.y = h1;
        lv.x = __float2bfloat16(v0 - __bfloat162float(h0));
        lv.y = __float2bfloat16(v1 - __bfloat162float(h1));
        size_t o = ((size_t)(n0 + nr) * rmul + radd) * K + k0 + c2 * 2;
        *reinterpret_cast<__nv_bfloat162*>(hi + o) = hv;
        *reinterpret_cast<__nv_bfloat162*>(lo + o) = lv;
    }
}

// =================== fused SIMT kernels =====================================
__global__ void rmsnorm_split(const float* __restrict__ x, const float* __restrict__ w,
                              __nv_bfloat16* __restrict__ hi, __nv_bfloat16* __restrict__ lo,
                              int d)
{
    long long t = blockIdx.x;
    const float* r = x + t * (long long)d;
    int tid = threadIdx.x;
    float ss = 0.f;
    for (int i = tid; i < d; i += blockDim.x) { float v = r[i]; ss += v * v; }
    for (int off = 16; off > 0; off >>= 1) ss += __shfl_xor_sync(0xffffffffu, ss, off);
    __shared__ float sh[8];
    if ((tid & 31) == 0) sh[tid >> 5] = ss;
    __syncthreads();
    float tot = 0.f;
    #pragma unroll
    for (int i = 0; i < 8; i++) tot += sh[i];
    float inv = rsqrtf(tot / d + 1e-6f);
    for (int i = tid; i < d; i += blockDim.x) {
        float v = r[i] * inv * w[i];
        __nv_bfloat16 h = __float2bfloat16(v);
        hi[t * (long long)d + i] = h;
        lo[t * (long long)d + i] = __float2bfloat16(v - __bfloat162float(h));
    }
}

// qkv split + head rmsnorm + rope; reads fused qkv|dwh|ddv rows (stride QKD)
__global__ void qkv_prep(const float* __restrict__ qkv,
                         const float* __restrict__ qw, const float* __restrict__ kw,
                         __nv_bfloat16* __restrict__ qh, __nv_bfloat16* __restrict__ ql,
                         __nv_bfloat16* __restrict__ kh, __nv_bfloat16* __restrict__ kl,
                         float* __restrict__ v)
{
    int n = blockIdx.x, t = blockIdx.y, d = threadIdx.x;
    const float* rowp = qkv + (long long)t * QKD + n * DHH;
    float qv = rowp[d], kv = rowp[DD + d], vv = rowp[2 * DD + d];

    float sq = qv * qv, sk = kv * kv;
    for (int off = 16; off > 0; off >>= 1) {
        sq += __shfl_xor_sync(0xffffffffu, sq, off);
        sk += __shfl_xor_sync(0xffffffffu, sk, off);
    }
    __shared__ float rq[4], rk[4];
    if ((d & 31) == 0) { rq[d >> 5] = sq; rk[d >> 5] = sk; }
    __syncthreads();
    float vq = (rq[0] + rq[1] + rq[2] + rq[3]) / (float)DHH;
    float vk = (rk[0] + rk[1] + rk[2] + rk[3]) / (float)DHH;
    float qn = qv * rsqrtf(vq + 1e-6f) * qw[d];
    float kn = kv * rsqrtf(vk + 1e-6f) * kw[d];

    __shared__ float sqb[DHH], skb[DHH];
    sqb[d] = qn; skb[d] = kn;
    __syncthreads();

    long long base = ((long long)n * TT + t) * DHH;
    v[base + d] = vv;
    if (d < 64) {
        float inv = powf(10000.f, -((float)d) / 64.f);
        float ang = (float)t * inv;
        float c, s;
        sincosf(ang, &s, &c);
        float q1 = sqb[d], q2 = sqb[64 + d];
        float k1 = skb[d], k2 = skb[64 + d];
        const float sc = 0.08838834764831845f;
        float qo0 = (q1 * c - q2 * s) * sc, qo1 = (q2 * c + q1 * s) * sc;
        float ko0 = (k1 * c - k2 * s),      ko1 = (k2 * c + k1 * s);
        __nv_bfloat16 h;
        h = __float2bfloat16(qo0); qh[base + 2*d]   = h; ql[base + 2*d]   = __float2bfloat16(qo0 - __bfloat162float(h));
        h = __float2bfloat16(qo1); qh[base + 2*d+1] = h; ql[base + 2*d+1] = __float2bfloat16(qo1 - __bfloat162float(h));
        h = __float2bfloat16(ko0); kh[base + 2*d]   = h; kl[base + 2*d]   = __float2bfloat16(ko0 - __bfloat162float(h));
        h = __float2bfloat16(ko1); kh[base + 2*d+1] = h; kl[base + 2*d+1] = __float2bfloat16(ko1 - __bfloat162float(h));
    }
}

// w projection; reads RAW dwh (pre-gelu) at qkvb cols [6144,6400), stride QKD
__global__ void wproj_k(const float* __restrict__ dwh_raw, const float* __restrict__ qkw,
                        float* __restrict__ w)
{
    int t = blockIdx.x;
    int tid = threadIdx.x;
    __shared__ float sh[256];
    {
        float xg = dwh_raw[(long long)t * QKD + tid];
        sh[tid] = 0.5f * xg * (1.f + erff(xg * 0.7071067811865475f));
    }
    __syncthreads();
    int c = tid >> 6, r = tid & 63, i = r >> 4, n = r & 15;
    float acc = 0.f;
    #pragma unroll 8
    for (int kk = 0; kk < 64; kk++)
        acc += sh[c * 64 + kk] * qkw[((c * 64 + kk) * 4 + i) * 16 + n];
    __shared__ float sw[256];
    sw[tid] = acc;
    __syncthreads();
    float out = acc;
    if (i < 2) {
        float ss = 0.f;
        #pragma unroll
        for (int m = 0; m < 16; m++) { float vv = sw[c * 64 + i * 16 + m]; ss += vv * vv; }
        out = acc * rsqrtf(ss / 16.f + 1e-6f);
    }
    w[(long long)t * 256 + tid] = out;
}

// cross_head_proj. POST=0: in-place on X, lower-triangle tiles.
// POST=1: writes bf16 split ph/pl, tiles covering s < 128-block edge of t.
template<int POST>
__global__ void crosshead_k(float* __restrict__ X, const float* __restrict__ W,
                            const float* __restrict__ ddv_raw,
                            int cq, int ck, int qoff, int koff,
                            __nv_bfloat16* __restrict__ ph, __nv_bfloat16* __restrict__ pl)
{
    if (POST == 0) { if (blockIdx.x > blockIdx.y) return; }
    else           { if ((blockIdx.x >> 2) > (blockIdx.y >> 2)) return; }
    __shared__ float q1[32][2][16], q2[32][2][16], qd[32][16];
    __shared__ float k1[32][2][16], k2[32][2][16], kd[32][16];
    int s0 = blockIdx.x * 32, t0 = blockIdx.y * 32;
    int tid = threadIdx.x;

    for (int idx = tid; idx < 32 * 64; idx += 256) {
        int row = idx >> 6, r = idx & 63;
        int i = r >> 4, n = r & 15;
        float vq = W[(long long)(t0 + row) * 256 + cq * 64 + i * 16 + n];
        float vk = W[(long long)(s0 + row) * 256 + ck * 64 + i * 16 + n];
        if (i < 2) { q1[row][i][n] = vq; k1[row][i][n] = vk; }
        else       { q2[row][i - 2][n] = vq; k2[row][i - 2][n] = vk; }
    }
    for (int idx = tid; idx < 32 * 16; idx += 256) {
        int row = idx >> 4, n = idx & 15;
        qd[row][n] = tanhf(ddv_raw[(long long)(t0 + row) * QKD + qoff + n]);
        kd[row][n] = tanhf(ddv_raw[(long long)(s0 + row) * QKD + koff + n]);
    }
    __syncthreads();

    const long long TSs = (long long)TT * SS;
    int si = tid & 31;
    int s = s0 + si;
    for (int tt = (tid >> 5); tt < 32; tt += 8) {
        long long base = (long long)(t0 + tt) * SS + s;
        float xv[16];
        #pragma unroll
        for (int n = 0; n < 16; n++) xv[n] = X[n * TSs + base];
        float a0 = 0.f, a1 = 0.f, b0 = 0.f, b1 = 0.f;
        #pragma unroll
        for (int n = 0; n < 16; n++) {
            a0 += xv[n] * q1[tt][0][n];
            a1 += xv[n] * q1[tt][1][n];
            b0 += xv[n] * k1[si][0][n];
            b1 += xv[n] * k1[si][1][n];
        }
        #pragma unroll
        for (int n = 0; n < 16; n++) {
            float ov = xv[n] * (1.f + qd[tt][n] + kd[si][n])
                     + a0 * q2[tt][0][n] + a1 * q2[tt][1][n]
                     + b0 * k2[si][0][n] + b1 * k2[si][1][n];
            if (POST == 0) {
                X[n * TSs + base] = ov;
            } else {
                __nv_bfloat16 h = __float2bfloat16(ov);
                ph[n * TSs + base] = h;
                pl[n * TSs + base] = __float2bfloat16(ov - __bfloat162float(h));
            }
        }
    }
}

// causal softmax with smem exp cache
__global__ void softmax_causal(float* __restrict__ X)
{
    __shared__ float ex[SS];
    int t = blockIdx.x, n = blockIdx.y;
    float* row = X + ((long long)n * TT + t) * (long long)SS;
    int valid = t + 1;
    int lim = ((t >> 7) + 1) << 7;
    int tid = threadIdx.x;
    __shared__ float sh[8];
    __shared__ float bcast;

    float m = -3.4e38f;
    for (int s = tid; s < valid; s += 256) m = fmaxf(m, row[s]);
    for (int off = 16; off > 0; off >>= 1) m = fmaxf(m, __shfl_xor_sync(0xffffffffu, m, off));
    if ((tid & 31) == 0) sh[tid >> 5] = m;
    __syncthreads();
    float mm = sh[0];
    #pragma unroll
    for (int i = 1; i < 8; i++) mm = fmaxf(mm, sh[i]);
    __syncthreads();

    float sum = 0.f;
    for (int s = tid; s < valid; s += 256) {
        float e = __expf(row[s] - mm);
        ex[s] = e;
        sum += e;
    }
    for (int off = 16; off > 0; off >>= 1) sum += __shfl_xor_sync(0xffffffffu, sum, off);
    if ((tid & 31) == 0) sh[tid >> 5] = sum;
    __syncthreads();
    if (tid == 0) {
        float tot = 0.f;
        #pragma unroll
        for (int i = 0; i < 8; i++) tot += sh[i];
        bcast = 1.f / tot;
    }
    __syncthreads();
    float inv = bcast;
    for (int s = tid; s < lim; s += 256)
        row[s] = (s < valid) ? ex[s] * inv : 0.f;
}

// =================== host orchestration =====================================
extern "C" void kernel_launch(void* const* d_in, const int* in_sizes, int n_in,
                              void* d_out, int out_size)
{
    const float* x       = (const float*)d_in[0];
    const float* attn_nw = (const float*)d_in[1];
    const float* wqkv    = (const float*)d_in[2];
    const float* q_nw    = (const float*)d_in[3];
    const float* k_nw    = (const float*)d_in[4];
    const float* dw1     = (const float*)d_in[5];
    const float* qkw     = (const float*)d_in[6];
    const float* dd      = (const float*)d_in[7];
    const float* wo      = (const float*)d_in[8];
    const float* ffn_nw  = (const float*)d_in[9];
    const float* w1f     = (const float*)d_in[10];
    const float* w3f     = (const float*)d_in[11];
    const float* w2f     = (const float*)d_in[12];
    float* out = (float*)d_out;

    static float *qkvb = nullptr, *v, *lg, *w, *h;
    static __nv_bfloat16 *wallT_h, *wallT_l, *woT_h, *woT_l, *w13T_h, *w13T_l,
                         *w2fT_h, *w2fT_l, *act_h, *act_l,
                         *qh, *ql, *kh, *kl, *vT_h, *vT_l, *ph, *pl;
    if (!qkvb) {
        cudaGetSymbolAddress((void**)&qkvb, g_qkv);
        cudaGetSymbolAddress((void**)&v,    g_v);
        cudaGetSymbolAddress((void**)&lg,   g_lg);
        cudaGetSymbolAddress((void**)&w,    g_w);
        cudaGetSymbolAddress((void**)&h,    g_h);
        cudaGetSymbolAddress((void**)&wallT_h, g_wallT_h);
        cudaGetSymbolAddress((void**)&wallT_l, g_wallT_l);
        cudaGetSymbolAddress((void**)&woT_h,   g_woT_h);
        cudaGetSymbolAddress((void**)&woT_l,   g_woT_l);
        cudaGetSymbolAddress((void**)&w13T_h,  g_w13T_h);
        cudaGetSymbolAddress((void**)&w13T_l,  g_w13T_l);
        cudaGetSymbolAddress((void**)&w2fT_h,  g_w2fT_h);
        cudaGetSymbolAddress((void**)&w2fT_l,  g_w2fT_l);
        cudaGetSymbolAddress((void**)&act_h,   g_act_h);
        cudaGetSymbolAddress((void**)&act_l,   g_act_l);
        cudaGetSymbolAddress((void**)&qh,   g_qh);
        cudaGetSymbolAddress((void**)&ql,   g_ql);
        cudaGetSymbolAddress((void**)&kh,   g_kh);
        cudaGetSymbolAddress((void**)&kl,   g_kl);
        cudaGetSymbolAddress((void**)&vT_h, g_vT_h);
        cudaGetSymbolAddress((void**)&vT_l, g_vT_l);
        cudaGetSymbolAddress((void**)&ph,   g_ph);
        cudaGetSymbolAddress((void**)&pl,   g_pl);
        cudaFuncSetAttribute(mma_gemm<0>, cudaFuncAttributeMaxDynamicSharedMemorySize, MM_SMEM);
        cudaFuncSetAttribute(mma_gemm<1>, cudaFuncAttributeMaxDynamicSharedMemorySize, MM_SMEM);
        cudaFuncSetAttribute(mma_gemm<3>, cudaFuncAttributeMaxDynamicSharedMemorySize, MM_SMEM);
        cudaFuncSetAttribute(mma_gemm<4>, cudaFuncAttributeMaxDynamicSharedMemorySize, MM_SMEM);
    }

    // weight conversions, 64x64 tiles (w1f -> even rows, w3f -> odd rows of w13T)
    convT<<<dim3(3 * DD / 64, DD / 64), 256>>>(wqkv, wallT_h, wallT_l, DD, 3 * DD, 0, 0, 1, 0);
    convT<<<dim3(256 / 64, DD / 64), 256>>>(dw1, wallT_h + (size_t)3 * DD * DD,
                                            wallT_l + (size_t)3 * DD * DD, DD, 256, 0, 0, 1, 0);
    convT<<<dim3(64 / 64, DD / 64), 256>>>(dd, wallT_h + (size_t)(3 * DD + 256) * DD,
                                           wallT_l + (size_t)(3 * DD + 256) * DD, DD, 64, 0, 0, 1, 0);
    convT<<<dim3(DD / 64, DD / 64), 256>>>(wo,  woT_h,  woT_l,  DD, DD, 0, 0, 1, 0);
    convT<<<dim3(FFD / 64, DD / 64), 256>>>(w1f, w13T_h, w13T_l, DD, FFD, 0, 0, 2, 0);
    convT<<<dim3(FFD / 64, DD / 64), 256>>>(w3f, w13T_h, w13T_l, DD, FFD, 0, 0, 2, 1);
    convT<<<dim3(DD / 64, FFD / 64), 256>>>(w2f, w2fT_h, w2fT_l, FFD, DD, 0, 0, 1, 0);

    // 1. hn = rmsnorm(x) -> split act
    rmsnorm_split<<<TT, 256>>>(x, attn_nw, act_h, act_l, DD);
    // 2. [qkv | dwh | ddv] = hn @ [wqkv | dw1 | dd]   (one merged GEMM)
    mma_gemm<0><<<dim3(QKD / 128, TT / 128), 256, MM_SMEM>>>(
        act_h, act_l, wallT_h, wallT_l, qkvb, nullptr, nullptr, nullptr,
        TT, QKD, DD, QKD, 0, 0, 0, 0);
    // 3. split + head rmsnorm + rope ; v fp32 then transpose-split
    qkv_prep<<<dim3(NHH, TT), 128>>>(qkvb, q_nw, k_nw, qh, ql, kh, kl, v);
    convT<<<dim3(DHH / 64, TT / 64, NHH), 256>>>(v, vT_h, vT_l, TT, DHH,
        (long long)TT * DHH, (long long)DHH * TT, 1, 0);
    // 4. dyn weights: gelu fused into wproj; tanh fused into crosshead loads
    wproj_k<<<TT, 256>>>(qkvb + 3 * DD, qkw, w);
    // 5. logits = q @ k^T (causal tiles only)
    mma_gemm<1><<<dim3(TT / 128, TT / 128, NHH), 256, MM_SMEM>>>(
        qh, ql, kh, kl, lg, nullptr, nullptr, nullptr, TT, TT, DHH, SS,
        (long long)TT * DHH, (long long)TT * DHH, (long long)TT * SS, 0);
    // 6-8. cross_head pre, softmax (smem exp cache), cross_head post -> ph/pl
    crosshead_k<0><<<dim3(SS / 32, TT / 32), 256>>>(
        lg, w, qkvb + 3 * DD + 256, 0, 1, 0, 16, nullptr, nullptr);
    softmax_causal<<<dim3(TT, NHH), 256>>>(lg);
    crosshead_k<1><<<dim3(SS / 32, TT / 32), 256>>>(
        lg, w, qkvb + 3 * DD + 256, 2, 3, 32, 48, ph, pl);
    // 9. o = probs @ v, 4-way split-K (fp32 partials into dead lg), then combine
    mma_gemm<4><<<dim3(4, TT / 128, NHH), 256, MM_SMEM>>>(
        ph, pl, vT_h, vT_l, lg, nullptr, nullptr, nullptr, TT, DHH, TT, DHH,
        (long long)TT * SS, (long long)DHH * TT, (long long)TT * DHH,
        (long long)NHH * TT * DHH);
    pv_combine<<<(int)(((long long)NHH * TT * DHH + 255) / 256), 256>>>(lg, act_h, act_l);
    // 10. h = x + o @ wo
    mma_gemm<0><<<dim3(DD / 128, TT / 128), 256, MM_SMEM>>>(
        act_h, act_l, woT_h, woT_l, h, x, nullptr, nullptr, TT, DD, DD, DD, 0, 0, 0, 0);
    // 11. ffn: rmsnorm->split(act), interleaved w1|w3 gemm + fused swiglu
    //     -> split act2 (ph/pl scratch, DISJOINT from A), then w2 gemm
    rmsnorm_split<<<TT, 256>>>(h, ffn_nw, act_h, act_l, DD);
    mma_gemm<3><<<dim3(2 * FFD / 128, TT / 128), 256, MM_SMEM>>>(
        act_h, act_l, w13T_h, w13T_l, nullptr, nullptr, ph, pl,
        TT, 2 * FFD, DD, FFD, 0, 0, 0, 0);
    mma_gemm<0><<<dim3(DD / 128, TT / 128), 256, MM_SMEM>>>(
        ph, pl, w2fT_h, w2fT_l, out, h, nullptr, nullptr, TT, DD, FFD, DD, 0, 0, 0, 0);
}

// round 16
// speedup vs baseline: 1.1326x; 1.0025x over previous
#include <cuda_runtime.h>
#include <cuda_bf16.h>
#include <math.h>
#include <stdint.h>

#define TT   2048
#define DD   2048
#define NHH  16
#define DHH  128
#define FFD  5632
#define SS   TT
#define QKD  6528   // 3*DD + 256 + 128 (qkv | dw1-hidden | dd)

// ---------------- scratch (static device globals; no allocation) ----------
static __device__ float g_qkv[(size_t)TT*QKD];   // qkv | dwh(raw) | ddv(raw)
static __device__ float g_v  [(size_t)NHH*TT*DHH];
static __device__ float g_lg [(size_t)NHH*TT*SS];   // logits; later PV split-K partials
static __device__ float g_w  [(size_t)TT*256];
static __device__ float g_h  [(size_t)TT*DD];

// bf16 split operands
static __device__ __nv_bfloat16 g_wallT_h[(size_t)QKD*DD];  // rows 6464..6527 stay zero
static __device__ __nv_bfloat16 g_wallT_l[(size_t)QKD*DD];
static __device__ __nv_bfloat16 g_woT_h  [(size_t)DD*DD];
static __device__ __nv_bfloat16 g_woT_l  [(size_t)DD*DD];
static __device__ __nv_bfloat16 g_w13T_h [(size_t)2*FFD*DD]; // interleaved: even=w1, odd=w3
static __device__ __nv_bfloat16 g_w13T_l [(size_t)2*FFD*DD];
static __device__ __nv_bfloat16 g_w2fT_h [(size_t)DD*FFD];
static __device__ __nv_bfloat16 g_w2fT_l [(size_t)DD*FFD];
static __device__ __nv_bfloat16 g_act_h  [(size_t)TT*FFD];
static __device__ __nv_bfloat16 g_act_l  [(size_t)TT*FFD];
static __device__ __nv_bfloat16 g_qh [(size_t)NHH*TT*DHH];
static __device__ __nv_bfloat16 g_ql [(size_t)NHH*TT*DHH];
static __device__ __nv_bfloat16 g_kh [(size_t)NHH*TT*DHH];
static __device__ __nv_bfloat16 g_kl [(size_t)NHH*TT*DHH];
static __device__ __nv_bfloat16 g_vT_h[(size_t)NHH*DHH*TT];
static __device__ __nv_bfloat16 g_vT_l[(size_t)NHH*DHH*TT];
static __device__ __nv_bfloat16 g_ph [(size_t)NHH*TT*SS];   // also reused as FFN act2_h
static __device__ __nv_bfloat16 g_pl [(size_t)NHH*TT*SS];   // also reused as FFN act2_l

// =================== asm helpers (plain-sm_103-legal) =======================
__device__ __forceinline__ uint32_t smem_u32(const void* p) {
    uint32_t a;
    asm("{ .reg .u64 t; cvta.to.shared.u64 t, %1; cvt.u32.u64 %0, t; }" : "=r"(a) : "l"(p));
    return a;
}
template<int NN> __device__ __forceinline__ void cp_wait() {
    asm volatile("cp.async.wait_group %0;" :: "n"(NN) : "memory");
}
__device__ __forceinline__ void cp_commit() {
    asm volatile("cp.async.commit_group;" ::: "memory");
}
__device__ __forceinline__ void cp16(uint32_t dst, const void* src) {
    asm volatile("cp.async.cg.shared.global [%0], [%1], 16;" :: "r"(dst), "l"(src) : "memory");
}
__device__ __forceinline__ void ldsm4(uint32_t* r, uint32_t addr) {
    asm volatile("ldmatrix.sync.aligned.m8n8.x4.shared.b16 {%0,%1,%2,%3}, [%4];"
                 : "=r"(r[0]), "=r"(r[1]), "=r"(r[2]), "=r"(r[3]) : "r"(addr));
}
__device__ __forceinline__ void mma_bf16(float* c, const uint32_t* a, const uint32_t* b) {
    asm volatile(
        "mma.sync.aligned.m16n8k16.row.col.f32.bf16.bf16.f32 "
        "{%0,%1,%2,%3}, {%4,%5,%6,%7}, {%8,%9}, {%0,%1,%2,%3};"
        : "+f"(c[0]), "+f"(c[1]), "+f"(c[2]), "+f"(c[3])
        : "r"(a[0]), "r"(a[1]), "r"(a[2]), "r"(a[3]), "r"(b[0]), "r"(b[1]));
}
#define SWZ(o) ((o) ^ (((o) >> 3) & 0x30))

__device__ __forceinline__ void split2(float2 v, __nv_bfloat162* hi, __nv_bfloat162* lo) {
    __nv_bfloat16 hx = __float2bfloat16(v.x), hy = __float2bfloat16(v.y);
    hi->x = hx; hi->y = hy;
    lo->x = __float2bfloat16(v.x - __bfloat162float(hx));
    lo->y = __float2bfloat16(v.y - __bfloat162float(hy));
}

// =================== mma.sync split-bf16 GEMM ================================
// MODE 0: plain  MODE 1: causal skip (logits)  MODE 3: GLU epilogue
// MODE 4: 4-way split-K causal PV (fp32 partials; blockIdx.x = quarter)
#define MM_STAGE 32768
#define MM_SMEM  (3 * MM_STAGE)

template<int MODE>
__global__ void __launch_bounds__(256, 2) mma_gemm(
    const __nv_bfloat16* __restrict__ Ahi, const __nv_bfloat16* __restrict__ Alo,
    const __nv_bfloat16* __restrict__ Bhi, const __nv_bfloat16* __restrict__ Blo,
    float* __restrict__ C, const float* __restrict__ R,
    __nv_bfloat16* __restrict__ Chi, __nv_bfloat16* __restrict__ Clo,
    int M, int N, int K, int ldc,
    long long sA, long long sB, long long sC, long long sX)
{
    const int bm = blockIdx.y * 128;
    const int bn = (MODE == 4) ? 0 : blockIdx.x * 128;
    const int kx = (MODE == 4) ? blockIdx.x : 0;
    if (MODE == 1 && bn > bm) return;

    extern __shared__ __align__(1024) char sm[];
    const int tid = threadIdx.x, lane = tid & 31, wid = tid >> 5;
    const int wm = wid & 3, wn = wid >> 2;
    const uint32_t sbase = smem_u32(sm);
    const long long z = blockIdx.z;
    Ahi += z * sA; Alo += z * sA;
    Bhi += z * sB; Blo += z * sB;
    C   += z * sC;
    if (MODE == 4) C += (long long)kx * sX;
    if (R)   R   += z * sC;
    if (Chi) { Chi += z * sC; Clo += z * sC; }

    const __nv_bfloat16* srcs[4] = {Ahi, Alo, Bhi, Blo};
    const int rowbase[4] = {bm, bm, bn, bn};

    auto issue = [&](int kc, int s) {
        #pragma unroll
        for (int i = 0; i < 8; i++) {
            int idx = tid + i * 256;
            int buf = idx >> 9, cc = idx & 511, row = cc >> 2, cb = cc & 3;
            const __nv_bfloat16* src =
                srcs[buf] + (size_t)(rowbase[buf] + row) * K + kc * 32 + cb * 8;
            uint32_t dst = sbase + s * MM_STAGE + buf * 8192 + SWZ(row * 64 + cb * 16);
            cp16(dst, src);
        }
        cp_commit();
    };

    float acc[2][8][4];
    #pragma unroll
    for (int a = 0; a < 2; a++)
        #pragma unroll
        for (int b = 0; b < 8; b++)
            #pragma unroll
            for (int q = 0; q < 4; q++) acc[a][b][q] = 0.f;

    const int Keff = (MODE == 4) ? ((bm + 128 < K) ? bm + 128 : K) : K;
    const int NC = Keff >> 5;
    int cBeg = 0, cEnd = NC;
    if (MODE == 4) {
        const int quart = NC >> 2;     // NC is a multiple of 4
        cBeg = kx * quart;
        cEnd = (kx == 3) ? NC : cBeg + quart;
    }
    issue(cBeg, 0);

    int s = 0;
    for (int c = cBeg; c < cEnd; c++) {
        if (c + 1 < cEnd) { issue(c + 1, (s == 2) ? 0 : s + 1); cp_wait<1>(); }
        else              { cp_wait<0>(); }
        __syncthreads();

        const uint32_t aB = sbase + s * MM_STAGE;
        const uint32_t bB = aB + 16384;
        #pragma unroll
        for (int ks = 0; ks < 2; ks++) {
            uint32_t ah[2][4], al[2][4];
            #pragma unroll
            for (int mt = 0; mt < 2; mt++) {
                int row = wm * 32 + mt * 16 + (lane & 15);
                uint32_t off = SWZ((uint32_t)(row * 64 + ks * 32 + ((lane >> 4) << 4)));
                ldsm4(ah[mt], aB + off);
                ldsm4(al[mt], aB + 8192 + off);
            }
            #pragma unroll
            for (int np = 0; np < 4; np++) {
                int rowb = wn * 64 + np * 16 + (lane & 7) + ((lane >> 4) << 3);
                uint32_t offb = SWZ((uint32_t)(rowb * 64 + ks * 32 + (((lane >> 3) & 1) << 4)));
                uint32_t bh[4], bl[4];
                ldsm4(bh, bB + offb);
                ldsm4(bl, bB + 8192 + offb);
                #pragma unroll
                for (int sub = 0; sub < 2; sub++) {
                    const int nt = np * 2 + sub;
                    #pragma unroll
                    for (int mt = 0; mt < 2; mt++) {
                        mma_bf16(acc[mt][nt], ah[mt], bh + sub * 2);
                        mma_bf16(acc[mt][nt], ah[mt], bl + sub * 2);
                        mma_bf16(acc[mt][nt], al[mt], bh + sub * 2);
                    }
                }
            }
        }
        s = (s == 2) ? 0 : s + 1;
    }

    #pragma unroll
    for (int mt = 0; mt < 2; mt++) {
        int r0 = bm + wm * 32 + mt * 16 + (lane >> 2);
        #pragma unroll
        for (int nt = 0; nt < 8; nt++) {
            if (MODE == 3) {
                int f = (bn >> 1) + wn * 32 + nt * 4 + (lane & 3);
                float a0 = acc[mt][nt][0], b0 = acc[mt][nt][1];
                float a1 = acc[mt][nt][2], b1 = acc[mt][nt][3];
                float v0 = (a0 / (1.f + __expf(-a0))) * b0;
                float v1 = (a1 / (1.f + __expf(-a1))) * b1;
                size_t i0 = (size_t)r0 * ldc + f;
                size_t i1 = i0 + 8 * (size_t)ldc;
                __nv_bfloat16 h0 = __float2bfloat16(v0);
                __nv_bfloat16 h1 = __float2bfloat16(v1);
                Chi[i0] = h0; Clo[i0] = __float2bfloat16(v0 - __bfloat162float(h0));
                Chi[i1] = h1; Clo[i1] = __float2bfloat16(v1 - __bfloat162float(h1));
                continue;
            }
            int col = bn + wn * 64 + nt * 8 + (lane & 3) * 2;
            size_t i0 = (size_t)r0 * ldc + col;
            size_t i1 = i0 + 8 * (size_t)ldc;
            float2 v0 = {acc[mt][nt][0], acc[mt][nt][1]};
            float2 v1 = {acc[mt][nt][2], acc[mt][nt][3]};
            if (MODE != 4 && Chi) {
                __nv_bfloat162 h0, l0, h1, l1;
                split2(v0, &h0, &l0);
                split2(v1, &h1, &l1);
                *(__nv_bfloat162*)(Chi + i0) = h0;
                *(__nv_bfloat162*)(Clo + i0) = l0;
                *(__nv_bfloat162*)(Chi + i1) = h1;
                *(__nv_bfloat162*)(Clo + i1) = l1;
            } else {
                if (R) {
                    float2 a = *(const float2*)(R + i0);
                    float2 b = *(const float2*)(R + i1);
                    v0.x += a.x; v0.y += a.y; v1.x += b.x; v1.y += b.y;
                }
                *(float2*)(C + i0) = v0;
                *(float2*)(C + i1) = v1;
            }
        }
    }
}

// PV split-K combine: act[t][h*128+d] = split(P0+P1+P2+P3)
__global__ void pv_combine(const float* __restrict__ P,
                           __nv_bfloat16* __restrict__ hi, __nv_bfloat16* __restrict__ lo)
{
    long long i = (long long)blockIdx.x * 256 + threadIdx.x;
    const long long TOT = (long long)NHH * TT * DHH;
    if (i < TOT) {
        float v = P[i] + P[i + TOT] + P[i + 2 * TOT] + P[i + 3 * TOT];
        long long h = i / ((long long)TT * DHH);
        long long r = i - h * (long long)TT * DHH;
        long long t = r / DHH, d = r - t * DHH;
        size_t o = (size_t)t * DD + h * DHH + d;
        __nv_bfloat16 hv = __float2bfloat16(v);
        hi[o] = hv;
        lo[o] = __float2bfloat16(v - __bfloat162float(hv));
    }
}

// =================== conversion kernels =====================================
// W[K][N] fp32 -> hi/lo[(N*rmul+radd)][K] bf16 (batched over z).
// 64x64 tile: float4 loads; bf16x4 (8B) vectorized stores.
__global__ void convT(const float* __restrict__ W, __nv_bfloat16* __restrict__ hi,
                      __nv_bfloat16* __restrict__ lo, int K, int N,
                      long long sW, long long sO, int rmul, int radd)
{
    W  += (long long)blockIdx.z * sW;
    hi += (long long)blockIdx.z * sO;
    lo += (long long)blockIdx.z * sO;
    __shared__ float t[64][65];
    int n0 = blockIdx.x * 64, k0 = blockIdx.y * 64;
    int tid = threadIdx.x;

    // load 64 k-rows x 64 n-cols, float4 per thread x4
    #pragma unroll
    for (int i = 0; i < 4; i++) {
        int idx = tid + i * 256;              // 0..1023
        int row = idx >> 4, c4 = idx & 15;    // row 0..63, c4 0..15
        float4 v = *reinterpret_cast<const float4*>(
            W + (size_t)(k0 + row) * N + n0 + c4 * 4);
        t[row][c4 * 4 + 0] = v.x;
        t[row][c4 * 4 + 1] = v.y;
        t[row][c4 * 4 + 2] = v.z;
        t[row][c4 * 4 + 3] = v.w;
    }
    __syncthreads();

    // store 64 n-rows x 64 k-cols as bf16x4 (8B) vectors
    #pragma unroll
    for (int i = 0; i < 4; i++) {
        int idx = tid + i * 256;              // 0..1023
        int nr = idx >> 4, c4 = idx & 15;     // nr 0..63, c4 0..15 (4 k each)
        float v0 = t[c4 * 4 + 0][nr];
        float v1 = t[c4 * 4 + 1][nr];
        float v2 = t[c4 * 4 + 2][nr];
        float v3 = t[c4 * 4 + 3][nr];
        __nv_bfloat16 h0 = __float2bfloat16(v0), h1 = __float2bfloat16(v1);
        __nv_bfloat16 h2 = __float2bfloat16(v2), h3 = __float2bfloat16(v3);
        __nv_bfloat162 hp0, hp1, lp0, lp1;
        hp0.x = h0; hp0.y = h1; hp1.x = h2; hp1.y = h3;
        lp0.x = __float2bfloat16(v0 - __bfloat162float(h0));
        lp0.y = __float2bfloat16(v1 - __bfloat162float(h1));
        lp1.x = __float2bfloat16(v2 - __bfloat162float(h2));
        lp1.y = __float2bfloat16(v3 - __bfloat162float(h3));
        uint2 hv, lv;
        hv.x = *reinterpret_cast<uint32_t*>(&hp0);
        hv.y = *reinterpret_cast<uint32_t*>(&hp1);
        lv.x = *reinterpret_cast<uint32_t*>(&lp0);
        lv.y = *reinterpret_cast<uint32_t*>(&lp1);
        size_t o = ((size_t)(n0 + nr) * rmul + radd) * K + k0 + c4 * 4;
        *reinterpret_cast<uint2*>(hi + o) = hv;
        *reinterpret_cast<uint2*>(lo + o) = lv;
    }
}

// =================== fused SIMT kernels =====================================
__global__ void rmsnorm_split(const float* __restrict__ x, const float* __restrict__ w,
                              __nv_bfloat16* __restrict__ hi, __nv_bfloat16* __restrict__ lo,
                              int d)
{
    long long t = blockIdx.x;
    const float* r = x + t * (long long)d;
    int tid = threadIdx.x;
    float ss = 0.f;
    for (int i = tid; i < d; i += blockDim.x) { float v = r[i]; ss += v * v; }
    for (int off = 16; off > 0; off >>= 1) ss += __shfl_xor_sync(0xffffffffu, ss, off);
    __shared__ float sh[8];
    if ((tid & 31) == 0) sh[tid >> 5] = ss;
    __syncthreads();
    float tot = 0.f;
    #pragma unroll
    for (int i = 0; i < 8; i++) tot += sh[i];
    float inv = rsqrtf(tot / d + 1e-6f);
    for (int i = tid; i < d; i += blockDim.x) {
        float v = r[i] * inv * w[i];
        __nv_bfloat16 h = __float2bfloat16(v);
        hi[t * (long long)d + i] = h;
        lo[t * (long long)d + i] = __float2bfloat16(v - __bfloat162float(h));
    }
}

// qkv split + head rmsnorm + rope; reads fused qkv|dwh|ddv rows (stride QKD)
__global__ void qkv_prep(const float* __restrict__ qkv,
                         const float* __restrict__ qw, const float* __restrict__ kw,
                         __nv_bfloat16* __restrict__ qh, __nv_bfloat16* __restrict__ ql,
                         __nv_bfloat16* __restrict__ kh, __nv_bfloat16* __restrict__ kl,
                         float* __restrict__ v)
{
    int n = blockIdx.x, t = blockIdx.y, d = threadIdx.x;
    const float* rowp = qkv + (long long)t * QKD + n * DHH;
    float qv = rowp[d], kv = rowp[DD + d], vv = rowp[2 * DD + d];

    float sq = qv * qv, sk = kv * kv;
    for (int off = 16; off > 0; off >>= 1) {
        sq += __shfl_xor_sync(0xffffffffu, sq, off);
        sk += __shfl_xor_sync(0xffffffffu, sk, off);
    }
    __shared__ float rq[4], rk[4];
    if ((d & 31) == 0) { rq[d >> 5] = sq; rk[d >> 5] = sk; }
    __syncthreads();
    float vq = (rq[0] + rq[1] + rq[2] + rq[3]) / (float)DHH;
    float vk = (rk[0] + rk[1] + rk[2] + rk[3]) / (float)DHH;
    float qn = qv * rsqrtf(vq + 1e-6f) * qw[d];
    float kn = kv * rsqrtf(vk + 1e-6f) * kw[d];

    __shared__ float sqb[DHH], skb[DHH];
    sqb[d] = qn; skb[d] = kn;
    __syncthreads();

    long long base = ((long long)n * TT + t) * DHH;
    v[base + d] = vv;
    if (d < 64) {
        float inv = powf(10000.f, -((float)d) / 64.f);
        float ang = (float)t * inv;
        float c, s;
        sincosf(ang, &s, &c);
        float q1 = sqb[d], q2 = sqb[64 + d];
        float k1 = skb[d], k2 = skb[64 + d];
        const float sc = 0.08838834764831845f;
        float qo0 = (q1 * c - q2 * s) * sc, qo1 = (q2 * c + q1 * s) * sc;
        float ko0 = (k1 * c - k2 * s),      ko1 = (k2 * c + k1 * s);
        __nv_bfloat16 h;
        h = __float2bfloat16(qo0); qh[base + 2*d]   = h; ql[base + 2*d]   = __float2bfloat16(qo0 - __bfloat162float(h));
        h = __float2bfloat16(qo1); qh[base + 2*d+1] = h; ql[base + 2*d+1] = __float2bfloat16(qo1 - __bfloat162float(h));
        h = __float2bfloat16(ko0); kh[base + 2*d]   = h; kl[base + 2*d]   = __float2bfloat16(ko0 - __bfloat162float(h));
        h = __float2bfloat16(ko1); kh[base + 2*d+1] = h; kl[base + 2*d+1] = __float2bfloat16(ko1 - __bfloat162float(h));
    }
}

// w projection; reads RAW dwh (pre-gelu) at qkvb cols [6144,6400), stride QKD
__global__ void wproj_k(const float* __restrict__ dwh_raw, const float* __restrict__ qkw,
                        float* __restrict__ w)
{
    int t = blockIdx.x;
    int tid = threadIdx.x;
    __shared__ float sh[256];
    {
        float xg = dwh_raw[(long long)t * QKD + tid];
        sh[tid] = 0.5f * xg * (1.f + erff(xg * 0.7071067811865475f));
    }
    __syncthreads();
    int c = tid >> 6, r = tid & 63, i = r >> 4, n = r & 15;
    float acc = 0.f;
    #pragma unroll 8
    for (int kk = 0; kk < 64; kk++)
        acc += sh[c * 64 + kk] * qkw[((c * 64 + kk) * 4 + i) * 16 + n];
    __shared__ float sw[256];
    sw[tid] = acc;
    __syncthreads();
    float out = acc;
    if (i < 2) {
        float ss = 0.f;
        #pragma unroll
        for (int m = 0; m < 16; m++) { float vv = sw[c * 64 + i * 16 + m]; ss += vv * vv; }
        out = acc * rsqrtf(ss / 16.f + 1e-6f);
    }
    w[(long long)t * 256 + tid] = out;
}

// cross_head_proj. POST=0: in-place on X, lower-triangle tiles.
// POST=1: writes bf16 split ph/pl, tiles covering s < 128-block edge of t.
template<int POST>
__global__ void crosshead_k(float* __restrict__ X, const float* __restrict__ W,
                            const float* __restrict__ ddv_raw,
                            int cq, int ck, int qoff, int koff,
                            __nv_bfloat16* __restrict__ ph, __nv_bfloat16* __restrict__ pl)
{
    if (POST == 0) { if (blockIdx.x > blockIdx.y) return; }
    else           { if ((blockIdx.x >> 2) > (blockIdx.y >> 2)) return; }
    __shared__ float q1[32][2][16], q2[32][2][16], qd[32][16];
    __shared__ float k1[32][2][16], k2[32][2][16], kd[32][16];
    int s0 = blockIdx.x * 32, t0 = blockIdx.y * 32;
    int tid = threadIdx.x;

    for (int idx = tid; idx < 32 * 64; idx += 256) {
        int row = idx >> 6, r = idx & 63;
        int i = r >> 4, n = r & 15;
        float vq = W[(long long)(t0 + row) * 256 + cq * 64 + i * 16 + n];
        float vk = W[(long long)(s0 + row) * 256 + ck * 64 + i * 16 + n];
        if (i < 2) { q1[row][i][n] = vq; k1[row][i][n] = vk; }
        else       { q2[row][i - 2][n] = vq; k2[row][i - 2][n] = vk; }
    }
    for (int idx = tid; idx < 32 * 16; idx += 256) {
        int row = idx >> 4, n = idx & 15;
        qd[row][n] = tanhf(ddv_raw[(long long)(t0 + row) * QKD + qoff + n]);
        kd[row][n] = tanhf(ddv_raw[(long long)(s0 + row) * QKD + koff + n]);
    }
    __syncthreads();

    const long long TSs = (long long)TT * SS;
    int si = tid & 31;
    int s = s0 + si;
    for (int tt = (tid >> 5); tt < 32; tt += 8) {
        long long base = (long long)(t0 + tt) * SS + s;
        float xv[16];
        #pragma unroll
        for (int n = 0; n < 16; n++) xv[n] = X[n * TSs + base];
        float a0 = 0.f, a1 = 0.f, b0 = 0.f, b1 = 0.f;
        #pragma unroll
        for (int n = 0; n < 16; n++) {
            a0 += xv[n] * q1[tt][0][n];
            a1 += xv[n] * q1[tt][1][n];
            b0 += xv[n] * k1[si][0][n];
            b1 += xv[n] * k1[si][1][n];
        }
        #pragma unroll
        for (int n = 0; n < 16; n++) {
            float ov = xv[n] * (1.f + qd[tt][n] + kd[si][n])
                     + a0 * q2[tt][0][n] + a1 * q2[tt][1][n]
                     + b0 * k2[si][0][n] + b1 * k2[si][1][n];
            if (POST == 0) {
                X[n * TSs + base] = ov;
            } else {
                __nv_bfloat16 h = __float2bfloat16(ov);
                ph[n * TSs + base] = h;
                pl[n * TSs + base] = __float2bfloat16(ov - __bfloat162float(h));
            }
        }
    }
}

// causal softmax with smem exp cache
__global__ void softmax_causal(float* __restrict__ X)
{
    __shared__ float ex[SS];
    int t = blockIdx.x, n = blockIdx.y;
    float* row = X + ((long long)n * TT + t) * (long long)SS;
    int valid = t + 1;
    int lim = ((t >> 7) + 1) << 7;
    int tid = threadIdx.x;
    __shared__ float sh[8];
    __shared__ float bcast;

    float m = -3.4e38f;
    for (int s = tid; s < valid; s += 256) m = fmaxf(m, row[s]);
    for (int off = 16; off > 0; off >>= 1) m = fmaxf(m, __shfl_xor_sync(0xffffffffu, m, off));
    if ((tid & 31) == 0) sh[tid >> 5] = m;
    __syncthreads();
    float mm = sh[0];
    #pragma unroll
    for (int i = 1; i < 8; i++) mm = fmaxf(mm, sh[i]);
    __syncthreads();

    float sum = 0.f;
    for (int s = tid; s < valid; s += 256) {
        float e = __expf(row[s] - mm);
        ex[s] = e;
        sum += e;
    }
    for (int off = 16; off > 0; off >>= 1) sum += __shfl_xor_sync(0xffffffffu, sum, off);
    if ((tid & 31) == 0) sh[tid >> 5] = sum;
    __syncthreads();
    if (tid == 0) {
        float tot = 0.f;
        #pragma unroll
        for (int i = 0; i < 8; i++) tot += sh[i];
        bcast = 1.f / tot;
    }
    __syncthreads();
    float inv = bcast;
    for (int s = tid; s < lim; s += 256)
        row[s] = (s < valid) ? ex[s] * inv : 0.f;
}

// =================== host orchestration =====================================
extern "C" void kernel_launch(void* const* d_in, const int* in_sizes, int n_in,
                              void* d_out, int out_size)
{
    const float* x       = (const float*)d_in[0];
    const float* attn_nw = (const float*)d_in[1];
    const float* wqkv    = (const float*)d_in[2];
    const float* q_nw    = (const float*)d_in[3];
    const float* k_nw    = (const float*)d_in[4];
    const float* dw1     = (const float*)d_in[5];
    const float* qkw     = (const float*)d_in[6];
    const float* dd      = (const float*)d_in[7];
    const float* wo      = (const float*)d_in[8];
    const float* ffn_nw  = (const float*)d_in[9];
    const float* w1f     = (const float*)d_in[10];
    const float* w3f     = (const float*)d_in[11];
    const float* w2f     = (const float*)d_in[12];
    float* out = (float*)d_out;

    static float *qkvb = nullptr, *v, *lg, *w, *h;
    static __nv_bfloat16 *wallT_h, *wallT_l, *woT_h, *woT_l, *w13T_h, *w13T_l,
                         *w2fT_h, *w2fT_l, *act_h, *act_l,
                         *qh, *ql, *kh, *kl, *vT_h, *vT_l, *ph, *pl;
    static cudaStream_t sB;
    static cudaEvent_t evF, evJ;
    if (!qkvb) {
        cudaGetSymbolAddress((void**)&qkvb, g_qkv);
        cudaGetSymbolAddress((void**)&v,    g_v);
        cudaGetSymbolAddress((void**)&lg,   g_lg);
        cudaGetSymbolAddress((void**)&w,    g_w);
        cudaGetSymbolAddress((void**)&h,    g_h);
        cudaGetSymbolAddress((void**)&wallT_h, g_wallT_h);
        cudaGetSymbolAddress((void**)&wallT_l, g_wallT_l);
        cudaGetSymbolAddress((void**)&woT_h,   g_woT_h);
        cudaGetSymbolAddress((void**)&woT_l,   g_woT_l);
        cudaGetSymbolAddress((void**)&w13T_h,  g_w13T_h);
        cudaGetSymbolAddress((void**)&w13T_l,  g_w13T_l);
        cudaGetSymbolAddress((void**)&w2fT_h,  g_w2fT_h);
        cudaGetSymbolAddress((void**)&w2fT_l,  g_w2fT_l);
        cudaGetSymbolAddress((void**)&act_h,   g_act_h);
        cudaGetSymbolAddress((void**)&act_l,   g_act_l);
        cudaGetSymbolAddress((void**)&qh,   g_qh);
        cudaGetSymbolAddress((void**)&ql,   g_ql);
        cudaGetSymbolAddress((void**)&kh,   g_kh);
        cudaGetSymbolAddress((void**)&kl,   g_kl);
        cudaGetSymbolAddress((void**)&vT_h, g_vT_h);
        cudaGetSymbolAddress((void**)&vT_l, g_vT_l);
        cudaGetSymbolAddress((void**)&ph,   g_ph);
        cudaGetSymbolAddress((void**)&pl,   g_pl);
        cudaFuncSetAttribute(mma_gemm<0>, cudaFuncAttributeMaxDynamicSharedMemorySize, MM_SMEM);
        cudaFuncSetAttribute(mma_gemm<1>, cudaFuncAttributeMaxDynamicSharedMemorySize, MM_SMEM);
        cudaFuncSetAttribute(mma_gemm<3>, cudaFuncAttributeMaxDynamicSharedMemorySize, MM_SMEM);
        cudaFuncSetAttribute(mma_gemm<4>, cudaFuncAttributeMaxDynamicSharedMemorySize, MM_SMEM);
        cudaStreamCreateWithFlags(&sB, cudaStreamNonBlocking);
        cudaEventCreateWithFlags(&evF, cudaEventDisableTiming);
        cudaEventCreateWithFlags(&evJ, cudaEventDisableTiming);
    }

    // ---- fork: FFN/wo weight conversions on side stream (joined before step 10)
    cudaEventRecord(evF, 0);
    cudaStreamWaitEvent(sB, evF, 0);
    convT<<<dim3(DD / 64, DD / 64), 256, 0, sB>>>(wo, woT_h, woT_l, DD, DD, 0, 0, 1, 0);
    convT<<<dim3(FFD / 64, DD / 64), 256, 0, sB>>>(w1f, w13T_h, w13T_l, DD, FFD, 0, 0, 2, 0);
    convT<<<dim3(FFD / 64, DD / 64), 256, 0, sB>>>(w3f, w13T_h, w13T_l, DD, FFD, 0, 0, 2, 1);
    convT<<<dim3(DD / 64, FFD / 64), 256, 0, sB>>>(w2f, w2fT_h, w2fT_l, FFD, DD, 0, 0, 1, 0);
    cudaEventRecord(evJ, sB);

    // ---- main stream: attention-path conversions + pipeline
    convT<<<dim3(3 * DD / 64, DD / 64), 256>>>(wqkv, wallT_h, wallT_l, DD, 3 * DD, 0, 0, 1, 0);
    convT<<<dim3(256 / 64, DD / 64), 256>>>(dw1, wallT_h + (size_t)3 * DD * DD,
                                            wallT_l + (size_t)3 * DD * DD, DD, 256, 0, 0, 1, 0);
    convT<<<dim3(64 / 64, DD / 64), 256>>>(dd, wallT_h + (size_t)(3 * DD + 256) * DD,
                                           wallT_l + (size_t)(3 * DD + 256) * DD, DD, 64, 0, 0, 1, 0);

    // 1. hn = rmsnorm(x) -> split act
    rmsnorm_split<<<TT, 256>>>(x, attn_nw, act_h, act_l, DD);
    // 2. [qkv | dwh | ddv] = hn @ [wqkv | dw1 | dd]   (one merged GEMM)
    mma_gemm<0><<<dim3(QKD / 128, TT / 128), 256, MM_SMEM>>>(
        act_h, act_l, wallT_h, wallT_l, qkvb, nullptr, nullptr, nullptr,
        TT, QKD, DD, QKD, 0, 0, 0, 0);
    // 3. split + head rmsnorm + rope ; v fp32 then transpose-split
    qkv_prep<<<dim3(NHH, TT), 128>>>(qkvb, q_nw, k_nw, qh, ql, kh, kl, v);
    convT<<<dim3(DHH / 64, TT / 64, NHH), 256>>>(v, vT_h, vT_l, TT, DHH,
        (long long)TT * DHH, (long long)DHH * TT, 1, 0);
    // 4. dyn weights: gelu fused into wproj; tanh fused into crosshead loads
    wproj_k<<<TT, 256>>>(qkvb + 3 * DD, qkw, w);
    // 5. logits = q @ k^T (causal tiles only)
    mma_gemm<1><<<dim3(TT / 128, TT / 128, NHH), 256, MM_SMEM>>>(
        qh, ql, kh, kl, lg, nullptr, nullptr, nullptr, TT, TT, DHH, SS,
        (long long)TT * DHH, (long long)TT * DHH, (long long)TT * SS, 0);
    // 6-8. cross_head pre, softmax (smem exp cache), cross_head post -> ph/pl
    crosshead_k<0><<<dim3(SS / 32, TT / 32), 256>>>(
        lg, w, qkvb + 3 * DD + 256, 0, 1, 0, 16, nullptr, nullptr);
    softmax_causal<<<dim3(TT, NHH), 256>>>(lg);
    crosshead_k<1><<<dim3(SS / 32, TT / 32), 256>>>(
        lg, w, qkvb + 3 * DD + 256, 2, 3, 32, 48, ph, pl);
    // 9. o = probs @ v, 4-way split-K (fp32 partials into dead lg), then combine
    mma_gemm<4><<<dim3(4, TT / 128, NHH), 256, MM_SMEM>>>(
        ph, pl, vT_h, vT_l, lg, nullptr, nullptr, nullptr, TT, DHH, TT, DHH,
        (long long)TT * SS, (long long)DHH * TT, (long long)TT * DHH,
        (long long)NHH * TT * DHH);
    pv_combine<<<(int)(((long long)NHH * TT * DHH + 255) / 256), 256>>>(lg, act_h, act_l);

    // ---- join side stream before its outputs are consumed
    cudaStreamWaitEvent(0, evJ, 0);

    // 10. h = x + o @ wo
    mma_gemm<0><<<dim3(DD / 128, TT / 128), 256, MM_SMEM>>>(
        act_h, act_l, woT_h, woT_l, h, x, nullptr, nullptr, TT, DD, DD, DD, 0, 0, 0, 0);
    // 11. ffn: rmsnorm->split(act), interleaved w1|w3 gemm + fused swiglu
    //     -> split act2 (ph/pl scratch, DISJOINT from A), then w2 gemm
    rmsnorm_split<<<TT, 256>>>(h, ffn_nw, act_h, act_l, DD);
    mma_gemm<3><<<dim3(2 * FFD / 128, TT / 128), 256, MM_SMEM>>>(
        act_h, act_l, w13T_h, w13T_l, nullptr, nullptr, ph, pl,
        TT, 2 * FFD, DD, FFD, 0, 0, 0, 0);
    mma_gemm<0><<<dim3(DD / 128, TT / 128), 256, MM_SMEM>>>(
        ph, pl, w2fT_h, w2fT_l, out, h, nullptr, nullptr, TT, DD, FFD, DD, 0, 0, 0, 0);
}

// round 17
// speedup vs baseline: 1.1379x; 1.0047x over previous
#include <cuda_runtime.h>
#include <cuda_bf16.h>
#include <math.h>
#include <stdint.h>

#define TT   2048
#define DD   2048
#define NHH  16
#define DHH  128
#define FFD  5632
#define SS   TT
#define QKD  6528   // 3*DD + 256 + 128 (qkv | dw1-hidden | dd)

// ---------------- scratch (static device globals; no allocation) ----------
static __device__ float g_qkv[(size_t)TT*QKD];   // qkv | dwh(raw) | ddv(raw)
static __device__ float g_v  [(size_t)NHH*TT*DHH];
static __device__ float g_lg [(size_t)NHH*TT*SS];   // logits; later PV split-K partials
static __device__ float g_w  [(size_t)TT*256];
static __device__ float g_h  [(size_t)TT*DD];

// bf16 split operands
static __device__ __nv_bfloat16 g_wallT_h[(size_t)QKD*DD];  // rows 6464..6527 stay zero
static __device__ __nv_bfloat16 g_wallT_l[(size_t)QKD*DD];
static __device__ __nv_bfloat16 g_woT_h  [(size_t)DD*DD];
static __device__ __nv_bfloat16 g_woT_l  [(size_t)DD*DD];
static __device__ __nv_bfloat16 g_w13T_h [(size_t)2*FFD*DD]; // interleaved: even=w1, odd=w3
static __device__ __nv_bfloat16 g_w13T_l [(size_t)2*FFD*DD];
static __device__ __nv_bfloat16 g_w2fT_h [(size_t)DD*FFD];
static __device__ __nv_bfloat16 g_w2fT_l [(size_t)DD*FFD];
static __device__ __nv_bfloat16 g_act_h  [(size_t)TT*FFD];
static __device__ __nv_bfloat16 g_act_l  [(size_t)TT*FFD];
static __device__ __nv_bfloat16 g_qh [(size_t)NHH*TT*DHH];
static __device__ __nv_bfloat16 g_ql [(size_t)NHH*TT*DHH];
static __device__ __nv_bfloat16 g_kh [(size_t)NHH*TT*DHH];
static __device__ __nv_bfloat16 g_kl [(size_t)NHH*TT*DHH];
static __device__ __nv_bfloat16 g_vT_h[(size_t)NHH*DHH*TT];
static __device__ __nv_bfloat16 g_vT_l[(size_t)NHH*DHH*TT];
static __device__ __nv_bfloat16 g_ph [(size_t)NHH*TT*SS];   // also reused as FFN act2_h
static __device__ __nv_bfloat16 g_pl [(size_t)NHH*TT*SS];   // also reused as FFN act2_l

// =================== asm helpers (plain-sm_103-legal) =======================
__device__ __forceinline__ uint32_t smem_u32(const void* p) {
    uint32_t a;
    asm("{ .reg .u64 t; cvta.to.shared.u64 t, %1; cvt.u32.u64 %0, t; }" : "=r"(a) : "l"(p));
    return a;
}
template<int NN> __device__ __forceinline__ void cp_wait() {
    asm volatile("cp.async.wait_group %0;" :: "n"(NN) : "memory");
}
__device__ __forceinline__ void cp_commit() {
    asm volatile("cp.async.commit_group;" ::: "memory");
}
__device__ __forceinline__ void cp16(uint32_t dst, const void* src) {
    asm volatile("cp.async.cg.shared.global [%0], [%1], 16;" :: "r"(dst), "l"(src) : "memory");
}
__device__ __forceinline__ void ldsm4(uint32_t* r, uint32_t addr) {
    asm volatile("ldmatrix.sync.aligned.m8n8.x4.shared.b16 {%0,%1,%2,%3}, [%4];"
                 : "=r"(r[0]), "=r"(r[1]), "=r"(r[2]), "=r"(r[3]) : "r"(addr));
}
__device__ __forceinline__ void mma_bf16(float* c, const uint32_t* a, const uint32_t* b) {
    asm volatile(
        "mma.sync.aligned.m16n8k16.row.col.f32.bf16.bf16.f32 "
        "{%0,%1,%2,%3}, {%4,%5,%6,%7}, {%8,%9}, {%0,%1,%2,%3};"
        : "+f"(c[0]), "+f"(c[1]), "+f"(c[2]), "+f"(c[3])
        : "r"(a[0]), "r"(a[1]), "r"(a[2]), "r"(a[3]), "r"(b[0]), "r"(b[1]));
}
#define SWZ(o) ((o) ^ (((o) >> 3) & 0x30))

__device__ __forceinline__ void split2(float2 v, __nv_bfloat162* hi, __nv_bfloat162* lo) {
    __nv_bfloat16 hx = __float2bfloat16(v.x), hy = __float2bfloat16(v.y);
    hi->x = hx; hi->y = hy;
    lo->x = __float2bfloat16(v.x - __bfloat162float(hx));
    lo->y = __float2bfloat16(v.y - __bfloat162float(hy));
}

// =================== mma.sync split-bf16 GEMM ================================
// MODE 0: plain  MODE 1: causal skip (logits)  MODE 3: GLU epilogue
// MODE 4: 4-way split-K causal PV (fp32 partials; blockIdx.x = quarter)
#define MM_STAGE 32768
#define MM_SMEM  (3 * MM_STAGE)

template<int MODE>
__global__ void __launch_bounds__(256, 2) mma_gemm(
    const __nv_bfloat16* __restrict__ Ahi, const __nv_bfloat16* __restrict__ Alo,
    const __nv_bfloat16* __restrict__ Bhi, const __nv_bfloat16* __restrict__ Blo,
    float* __restrict__ C, const float* __restrict__ R,
    __nv_bfloat16* __restrict__ Chi, __nv_bfloat16* __restrict__ Clo,
    int M, int N, int K, int ldc,
    long long sA, long long sB, long long sC, long long sX)
{
    const int bm = blockIdx.y * 128;
    const int bn = (MODE == 4) ? 0 : blockIdx.x * 128;
    const int kx = (MODE == 4) ? blockIdx.x : 0;
    if (MODE == 1 && bn > bm) return;

    extern __shared__ __align__(1024) char sm[];
    const int tid = threadIdx.x, lane = tid & 31, wid = tid >> 5;
    const int wm = wid & 3, wn = wid >> 2;
    const uint32_t sbase = smem_u32(sm);
    const long long z = blockIdx.z;
    Ahi += z * sA; Alo += z * sA;
    Bhi += z * sB; Blo += z * sB;
    C   += z * sC;
    if (MODE == 4) C += (long long)kx * sX;
    if (R)   R   += z * sC;
    if (Chi) { Chi += z * sC; Clo += z * sC; }

    const __nv_bfloat16* srcs[4] = {Ahi, Alo, Bhi, Blo};
    const int rowbase[4] = {bm, bm, bn, bn};

    auto issue = [&](int kc, int s) {
        #pragma unroll
        for (int i = 0; i < 8; i++) {
            int idx = tid + i * 256;
            int buf = idx >> 9, cc = idx & 511, row = cc >> 2, cb = cc & 3;
            const __nv_bfloat16* src =
                srcs[buf] + (size_t)(rowbase[buf] + row) * K + kc * 32 + cb * 8;
            uint32_t dst = sbase + s * MM_STAGE + buf * 8192 + SWZ(row * 64 + cb * 16);
            cp16(dst, src);
        }
        cp_commit();
    };

    float acc[2][8][4];
    #pragma unroll
    for (int a = 0; a < 2; a++)
        #pragma unroll
        for (int b = 0; b < 8; b++)
            #pragma unroll
            for (int q = 0; q < 4; q++) acc[a][b][q] = 0.f;

    const int Keff = (MODE == 4) ? ((bm + 128 < K) ? bm + 128 : K) : K;
    const int NC = Keff >> 5;
    int cBeg = 0, cEnd = NC;
    if (MODE == 4) {
        const int quart = NC >> 2;     // NC is a multiple of 4
        cBeg = kx * quart;
        cEnd = (kx == 3) ? NC : cBeg + quart;
    }
    issue(cBeg, 0);

    int s = 0;
    for (int c = cBeg; c < cEnd; c++) {
        if (c + 1 < cEnd) { issue(c + 1, (s == 2) ? 0 : s + 1); cp_wait<1>(); }
        else              { cp_wait<0>(); }
        __syncthreads();

        const uint32_t aB = sbase + s * MM_STAGE;
        const uint32_t bB = aB + 16384;
        #pragma unroll
        for (int ks = 0; ks < 2; ks++) {
            uint32_t ah[2][4], al[2][4];
            #pragma unroll
            for (int mt = 0; mt < 2; mt++) {
                int row = wm * 32 + mt * 16 + (lane & 15);
                uint32_t off = SWZ((uint32_t)(row * 64 + ks * 32 + ((lane >> 4) << 4)));
                ldsm4(ah[mt], aB + off);
                ldsm4(al[mt], aB + 8192 + off);
            }
            #pragma unroll
            for (int np = 0; np < 4; np++) {
                int rowb = wn * 64 + np * 16 + (lane & 7) + ((lane >> 4) << 3);
                uint32_t offb = SWZ((uint32_t)(rowb * 64 + ks * 32 + (((lane >> 3) & 1) << 4)));
                uint32_t bh[4], bl[4];
                ldsm4(bh, bB + offb);
                ldsm4(bl, bB + 8192 + offb);
                #pragma unroll
                for (int sub = 0; sub < 2; sub++) {
                    const int nt = np * 2 + sub;
                    #pragma unroll
                    for (int mt = 0; mt < 2; mt++) {
                        mma_bf16(acc[mt][nt], ah[mt], bh + sub * 2);
                        mma_bf16(acc[mt][nt], ah[mt], bl + sub * 2);
                        mma_bf16(acc[mt][nt], al[mt], bh + sub * 2);
                    }
                }
            }
        }
        s = (s == 2) ? 0 : s + 1;
    }

    #pragma unroll
    for (int mt = 0; mt < 2; mt++) {
        int r0 = bm + wm * 32 + mt * 16 + (lane >> 2);
        #pragma unroll
        for (int nt = 0; nt < 8; nt++) {
            if (MODE == 3) {
                int f = (bn >> 1) + wn * 32 + nt * 4 + (lane & 3);
                float a0 = acc[mt][nt][0], b0 = acc[mt][nt][1];
                float a1 = acc[mt][nt][2], b1 = acc[mt][nt][3];
                float v0 = (a0 / (1.f + __expf(-a0))) * b0;
                float v1 = (a1 / (1.f + __expf(-a1))) * b1;
                size_t i0 = (size_t)r0 * ldc + f;
                size_t i1 = i0 + 8 * (size_t)ldc;
                __nv_bfloat16 h0 = __float2bfloat16(v0);
                __nv_bfloat16 h1 = __float2bfloat16(v1);
                Chi[i0] = h0; Clo[i0] = __float2bfloat16(v0 - __bfloat162float(h0));
                Chi[i1] = h1; Clo[i1] = __float2bfloat16(v1 - __bfloat162float(h1));
                continue;
            }
            int col = bn + wn * 64 + nt * 8 + (lane & 3) * 2;
            size_t i0 = (size_t)r0 * ldc + col;
            size_t i1 = i0 + 8 * (size_t)ldc;
            float2 v0 = {acc[mt][nt][0], acc[mt][nt][1]};
            float2 v1 = {acc[mt][nt][2], acc[mt][nt][3]};
            if (MODE != 4 && Chi) {
                __nv_bfloat162 h0, l0, h1, l1;
                split2(v0, &h0, &l0);
                split2(v1, &h1, &l1);
                *(__nv_bfloat162*)(Chi + i0) = h0;
                *(__nv_bfloat162*)(Clo + i0) = l0;
                *(__nv_bfloat162*)(Chi + i1) = h1;
                *(__nv_bfloat162*)(Clo + i1) = l1;
            } else {
                if (R) {
                    float2 a = *(const float2*)(R + i0);
                    float2 b = *(const float2*)(R + i1);
                    v0.x += a.x; v0.y += a.y; v1.x += b.x; v1.y += b.y;
                }
                *(float2*)(C + i0) = v0;
                *(float2*)(C + i1) = v1;
            }
        }
    }
}

// PV split-K combine: act[t][h*128+d] = split(P0+P1+P2+P3)
__global__ void pv_combine(const float* __restrict__ P,
                           __nv_bfloat16* __restrict__ hi, __nv_bfloat16* __restrict__ lo)
{
    long long i = (long long)blockIdx.x * 256 + threadIdx.x;
    const long long TOT = (long long)NHH * TT * DHH;
    if (i < TOT) {
        float v = P[i] + P[i + TOT] + P[i + 2 * TOT] + P[i + 3 * TOT];
        long long h = i / ((long long)TT * DHH);
        long long r = i - h * (long long)TT * DHH;
        long long t = r / DHH, d = r - t * DHH;
        size_t o = (size_t)t * DD + h * DHH + d;
        __nv_bfloat16 hv = __float2bfloat16(v);
        hi[o] = hv;
        lo[o] = __float2bfloat16(v - __bfloat162float(hv));
    }
}

// =================== conversion kernels =====================================
// W[K][N] fp32 -> hi/lo[(N*rmul+radd)][K] bf16 (batched over z).
// 64x64 tile: float4 loads; bf16x4 (8B) vectorized stores.
__global__ void convT(const float* __restrict__ W, __nv_bfloat16* __restrict__ hi,
                      __nv_bfloat16* __restrict__ lo, int K, int N,
                      long long sW, long long sO, int rmul, int radd)
{
    W  += (long long)blockIdx.z * sW;
    hi += (long long)blockIdx.z * sO;
    lo += (long long)blockIdx.z * sO;
    __shared__ float t[64][65];
    int n0 = blockIdx.x * 64, k0 = blockIdx.y * 64;
    int tid = threadIdx.x;

    #pragma unroll
    for (int i = 0; i < 4; i++) {
        int idx = tid + i * 256;
        int row = idx >> 4, c4 = idx & 15;
        float4 v = *reinterpret_cast<const float4*>(
            W + (size_t)(k0 + row) * N + n0 + c4 * 4);
        t[row][c4 * 4 + 0] = v.x;
        t[row][c4 * 4 + 1] = v.y;
        t[row][c4 * 4 + 2] = v.z;
        t[row][c4 * 4 + 3] = v.w;
    }
    __syncthreads();

    #pragma unroll
    for (int i = 0; i < 4; i++) {
        int idx = tid + i * 256;
        int nr = idx >> 4, c4 = idx & 15;
        float v0 = t[c4 * 4 + 0][nr];
        float v1 = t[c4 * 4 + 1][nr];
        float v2 = t[c4 * 4 + 2][nr];
        float v3 = t[c4 * 4 + 3][nr];
        __nv_bfloat16 h0 = __float2bfloat16(v0), h1 = __float2bfloat16(v1);
        __nv_bfloat16 h2 = __float2bfloat16(v2), h3 = __float2bfloat16(v3);
        __nv_bfloat162 hp0, hp1, lp0, lp1;
        hp0.x = h0; hp0.y = h1; hp1.x = h2; hp1.y = h3;
        lp0.x = __float2bfloat16(v0 - __bfloat162float(h0));
        lp0.y = __float2bfloat16(v1 - __bfloat162float(h1));
        lp1.x = __float2bfloat16(v2 - __bfloat162float(h2));
        lp1.y = __float2bfloat16(v3 - __bfloat162float(h3));
        uint2 hv, lv;
        hv.x = *reinterpret_cast<uint32_t*>(&hp0);
        hv.y = *reinterpret_cast<uint32_t*>(&hp1);
        lv.x = *reinterpret_cast<uint32_t*>(&lp0);
        lv.y = *reinterpret_cast<uint32_t*>(&lp1);
        size_t o = ((size_t)(n0 + nr) * rmul + radd) * K + k0 + c4 * 4;
        *reinterpret_cast<uint2*>(hi + o) = hv;
        *reinterpret_cast<uint2*>(lo + o) = lv;
    }
}

// =================== fused SIMT kernels =====================================
__global__ void rmsnorm_split(const float* __restrict__ x, const float* __restrict__ w,
                              __nv_bfloat16* __restrict__ hi, __nv_bfloat16* __restrict__ lo,
                              int d)
{
    long long t = blockIdx.x;
    const float* r = x + t * (long long)d;
    int tid = threadIdx.x;
    float ss = 0.f;
    for (int i = tid; i < d; i += blockDim.x) { float v = r[i]; ss += v * v; }
    for (int off = 16; off > 0; off >>= 1) ss += __shfl_xor_sync(0xffffffffu, ss, off);
    __shared__ float sh[8];
    if ((tid & 31) == 0) sh[tid >> 5] = ss;
    __syncthreads();
    float tot = 0.f;
    #pragma unroll
    for (int i = 0; i < 8; i++) tot += sh[i];
    float inv = rsqrtf(tot / d + 1e-6f);
    for (int i = tid; i < d; i += blockDim.x) {
        float v = r[i] * inv * w[i];
        __nv_bfloat16 h = __float2bfloat16(v);
        hi[t * (long long)d + i] = h;
        lo[t * (long long)d + i] = __float2bfloat16(v - __bfloat162float(h));
    }
}

// qkv split + head rmsnorm + rope; reads fused qkv|dwh|ddv rows (stride QKD)
__global__ void qkv_prep(const float* __restrict__ qkv,
                         const float* __restrict__ qw, const float* __restrict__ kw,
                         __nv_bfloat16* __restrict__ qh, __nv_bfloat16* __restrict__ ql,
                         __nv_bfloat16* __restrict__ kh, __nv_bfloat16* __restrict__ kl,
                         float* __restrict__ v)
{
    int n = blockIdx.x, t = blockIdx.y, d = threadIdx.x;
    const float* rowp = qkv + (long long)t * QKD + n * DHH;
    float qv = rowp[d], kv = rowp[DD + d], vv = rowp[2 * DD + d];

    float sq = qv * qv, sk = kv * kv;
    for (int off = 16; off > 0; off >>= 1) {
        sq += __shfl_xor_sync(0xffffffffu, sq, off);
        sk += __shfl_xor_sync(0xffffffffu, sk, off);
    }
    __shared__ float rq[4], rk[4];
    if ((d & 31) == 0) { rq[d >> 5] = sq; rk[d >> 5] = sk; }
    __syncthreads();
    float vq = (rq[0] + rq[1] + rq[2] + rq[3]) / (float)DHH;
    float vk = (rk[0] + rk[1] + rk[2] + rk[3]) / (float)DHH;
    float qn = qv * rsqrtf(vq + 1e-6f) * qw[d];
    float kn = kv * rsqrtf(vk + 1e-6f) * kw[d];

    __shared__ float sqb[DHH], skb[DHH];
    sqb[d] = qn; skb[d] = kn;
    __syncthreads();

    long long base = ((long long)n * TT + t) * DHH;
    v[base + d] = vv;
    if (d < 64) {
        float inv = powf(10000.f, -((float)d) / 64.f);
        float ang = (float)t * inv;
        float c, s;
        sincosf(ang, &s, &c);
        float q1 = sqb[d], q2 = sqb[64 + d];
        float k1 = skb[d], k2 = skb[64 + d];
        const float sc = 0.08838834764831845f;
        float qo0 = (q1 * c - q2 * s) * sc, qo1 = (q2 * c + q1 * s) * sc;
        float ko0 = (k1 * c - k2 * s),      ko1 = (k2 * c + k1 * s);
        __nv_bfloat16 h;
        h = __float2bfloat16(qo0); qh[base + 2*d]   = h; ql[base + 2*d]   = __float2bfloat16(qo0 - __bfloat162float(h));
        h = __float2bfloat16(qo1); qh[base + 2*d+1] = h; ql[base + 2*d+1] = __float2bfloat16(qo1 - __bfloat162float(h));
        h = __float2bfloat16(ko0); kh[base + 2*d]   = h; kl[base + 2*d]   = __float2bfloat16(ko0 - __bfloat162float(h));
        h = __float2bfloat16(ko1); kh[base + 2*d+1] = h; kl[base + 2*d+1] = __float2bfloat16(ko1 - __bfloat162float(h));
    }
}

// w projection; reads RAW dwh (pre-gelu) at qkvb cols [6144,6400), stride QKD
__global__ void wproj_k(const float* __restrict__ dwh_raw, const float* __restrict__ qkw,
                        float* __restrict__ w)
{
    int t = blockIdx.x;
    int tid = threadIdx.x;
    __shared__ float sh[256];
    {
        float xg = dwh_raw[(long long)t * QKD + tid];
        sh[tid] = 0.5f * xg * (1.f + erff(xg * 0.7071067811865475f));
    }
    __syncthreads();
    int c = tid >> 6, r = tid & 63, i = r >> 4, n = r & 15;
    float acc = 0.f;
    #pragma unroll 8
    for (int kk = 0; kk < 64; kk++)
        acc += sh[c * 64 + kk] * qkw[((c * 64 + kk) * 4 + i) * 16 + n];
    __shared__ float sw[256];
    sw[tid] = acc;
    __syncthreads();
    float out = acc;
    if (i < 2) {
        float ss = 0.f;
        #pragma unroll
        for (int m = 0; m < 16; m++) { float vv = sw[c * 64 + i * 16 + m]; ss += vv * vv; }
        out = acc * rsqrtf(ss / 16.f + 1e-6f);
    }
    w[(long long)t * 256 + tid] = out;
}

// cross_head_proj. POST=0: in-place on X, lower-triangle tiles.
// POST=1: writes bf16 split ph/pl, tiles covering s < 128-block edge of t.
template<int POST>
__global__ void crosshead_k(float* __restrict__ X, const float* __restrict__ W,
                            const float* __restrict__ ddv_raw,
                            int cq, int ck, int qoff, int koff,
                            __nv_bfloat16* __restrict__ ph, __nv_bfloat16* __restrict__ pl)
{
    if (POST == 0) { if (blockIdx.x > blockIdx.y) return; }
    else           { if ((blockIdx.x >> 2) > (blockIdx.y >> 2)) return; }
    __shared__ float q1[32][2][16], q2[32][2][16], qd[32][16];
    __shared__ float k1[32][2][16], k2[32][2][16], kd[32][16];
    int s0 = blockIdx.x * 32, t0 = blockIdx.y * 32;
    int tid = threadIdx.x;

    for (int idx = tid; idx < 32 * 64; idx += 256) {
        int row = idx >> 6, r = idx & 63;
        int i = r >> 4, n = r & 15;
        float vq = W[(long long)(t0 + row) * 256 + cq * 64 + i * 16 + n];
        float vk = W[(long long)(s0 + row) * 256 + ck * 64 + i * 16 + n];
        if (i < 2) { q1[row][i][n] = vq; k1[row][i][n] = vk; }
        else       { q2[row][i - 2][n] = vq; k2[row][i - 2][n] = vk; }
    }
    for (int idx = tid; idx < 32 * 16; idx += 256) {
        int row = idx >> 4, n = idx & 15;
        qd[row][n] = tanhf(ddv_raw[(long long)(t0 + row) * QKD + qoff + n]);
        kd[row][n] = tanhf(ddv_raw[(long long)(s0 + row) * QKD + koff + n]);
    }
    __syncthreads();

    const long long TSs = (long long)TT * SS;
    int si = tid & 31;
    int s = s0 + si;
    for (int tt = (tid >> 5); tt < 32; tt += 8) {
        long long base = (long long)(t0 + tt) * SS + s;
        float xv[16];
        #pragma unroll
        for (int n = 0; n < 16; n++) xv[n] = X[n * TSs + base];
        float a0 = 0.f, a1 = 0.f, b0 = 0.f, b1 = 0.f;
        #pragma unroll
        for (int n = 0; n < 16; n++) {
            a0 += xv[n] * q1[tt][0][n];
            a1 += xv[n] * q1[tt][1][n];
            b0 += xv[n] * k1[si][0][n];
            b1 += xv[n] * k1[si][1][n];
        }
        #pragma unroll
        for (int n = 0; n < 16; n++) {
            float ov = xv[n] * (1.f + qd[tt][n] + kd[si][n])
                     + a0 * q2[tt][0][n] + a1 * q2[tt][1][n]
                     + b0 * k2[si][0][n] + b1 * k2[si][1][n];
            if (POST == 0) {
                X[n * TSs + base] = ov;
            } else {
                __nv_bfloat16 h = __float2bfloat16(ov);
                ph[n * TSs + base] = h;
                pl[n * TSs + base] = __float2bfloat16(ov - __bfloat162float(h));
            }
        }
    }
}

// causal softmax with smem exp cache
__global__ void softmax_causal(float* __restrict__ X)
{
    __shared__ float ex[SS];
    int t = blockIdx.x, n = blockIdx.y;
    float* row = X + ((long long)n * TT + t) * (long long)SS;
    int valid = t + 1;
    int lim = ((t >> 7) + 1) << 7;
    int tid = threadIdx.x;
    __shared__ float sh[8];
    __shared__ float bcast;

    float m = -3.4e38f;
    for (int s = tid; s < valid; s += 256) m = fmaxf(m, row[s]);
    for (int off = 16; off > 0; off >>= 1) m = fmaxf(m, __shfl_xor_sync(0xffffffffu, m, off));
    if ((tid & 31) == 0) sh[tid >> 5] = m;
    __syncthreads();
    float mm = sh[0];
    #pragma unroll
    for (int i = 1; i < 8; i++) mm = fmaxf(mm, sh[i]);
    __syncthreads();

    float sum = 0.f;
    for (int s = tid; s < valid; s += 256) {
        float e = __expf(row[s] - mm);
        ex[s] = e;
        sum += e;
    }
    for (int off = 16; off > 0; off >>= 1) sum += __shfl_xor_sync(0xffffffffu, sum, off);
    if ((tid & 31) == 0) sh[tid >> 5] = sum;
    __syncthreads();
    if (tid == 0) {
        float tot = 0.f;
        #pragma unroll
        for (int i = 0; i < 8; i++) tot += sh[i];
        bcast = 1.f / tot;
    }
    __syncthreads();
    float inv = bcast;
    for (int s = tid; s < lim; s += 256)
        row[s] = (s < valid) ? ex[s] * inv : 0.f;
}

// =================== host orchestration =====================================
extern "C" void kernel_launch(void* const* d_in, const int* in_sizes, int n_in,
                              void* d_out, int out_size)
{
    const float* x       = (const float*)d_in[0];
    const float* attn_nw = (const float*)d_in[1];
    const float* wqkv    = (const float*)d_in[2];
    const float* q_nw    = (const float*)d_in[3];
    const float* k_nw    = (const float*)d_in[4];
    const float* dw1     = (const float*)d_in[5];
    const float* qkw     = (const float*)d_in[6];
    const float* dd      = (const float*)d_in[7];
    const float* wo      = (const float*)d_in[8];
    const float* ffn_nw  = (const float*)d_in[9];
    const float* w1f     = (const float*)d_in[10];
    const float* w3f     = (const float*)d_in[11];
    const float* w2f     = (const float*)d_in[12];
    float* out = (float*)d_out;

    static float *qkvb = nullptr, *v, *lg, *w, *h;
    static __nv_bfloat16 *wallT_h, *wallT_l, *woT_h, *woT_l, *w13T_h, *w13T_l,
                         *w2fT_h, *w2fT_l, *act_h, *act_l,
                         *qh, *ql, *kh, *kl, *vT_h, *vT_l, *ph, *pl;
    static cudaStream_t sB;
    static cudaEvent_t evF, evJ, evA, evW, evB, evV;
    if (!qkvb) {
        cudaGetSymbolAddress((void**)&qkvb, g_qkv);
        cudaGetSymbolAddress((void**)&v,    g_v);
        cudaGetSymbolAddress((void**)&lg,   g_lg);
        cudaGetSymbolAddress((void**)&w,    g_w);
        cudaGetSymbolAddress((void**)&h,    g_h);
        cudaGetSymbolAddress((void**)&wallT_h, g_wallT_h);
        cudaGetSymbolAddress((void**)&wallT_l, g_wallT_l);
        cudaGetSymbolAddress((void**)&woT_h,   g_woT_h);
        cudaGetSymbolAddress((void**)&woT_l,   g_woT_l);
        cudaGetSymbolAddress((void**)&w13T_h,  g_w13T_h);
        cudaGetSymbolAddress((void**)&w13T_l,  g_w13T_l);
        cudaGetSymbolAddress((void**)&w2fT_h,  g_w2fT_h);
        cudaGetSymbolAddress((void**)&w2fT_l,  g_w2fT_l);
        cudaGetSymbolAddress((void**)&act_h,   g_act_h);
        cudaGetSymbolAddress((void**)&act_l,   g_act_l);
        cudaGetSymbolAddress((void**)&qh,   g_qh);
        cudaGetSymbolAddress((void**)&ql,   g_ql);
        cudaGetSymbolAddress((void**)&kh,   g_kh);
        cudaGetSymbolAddress((void**)&kl,   g_kl);
        cudaGetSymbolAddress((void**)&vT_h, g_vT_h);
        cudaGetSymbolAddress((void**)&vT_l, g_vT_l);
        cudaGetSymbolAddress((void**)&ph,   g_ph);
        cudaGetSymbolAddress((void**)&pl,   g_pl);
        cudaFuncSetAttribute(mma_gemm<0>, cudaFuncAttributeMaxDynamicSharedMemorySize, MM_SMEM);
        cudaFuncSetAttribute(mma_gemm<1>, cudaFuncAttributeMaxDynamicSharedMemorySize, MM_SMEM);
        cudaFuncSetAttribute(mma_gemm<3>, cudaFuncAttributeMaxDynamicSharedMemorySize, MM_SMEM);
        cudaFuncSetAttribute(mma_gemm<4>, cudaFuncAttributeMaxDynamicSharedMemorySize, MM_SMEM);
        cudaStreamCreateWithFlags(&sB, cudaStreamNonBlocking);
        cudaEventCreateWithFlags(&evF, cudaEventDisableTiming);
        cudaEventCreateWithFlags(&evJ, cudaEventDisableTiming);
        cudaEventCreateWithFlags(&evA, cudaEventDisableTiming);
        cudaEventCreateWithFlags(&evW, cudaEventDisableTiming);
        cudaEventCreateWithFlags(&evB, cudaEventDisableTiming);
        cudaEventCreateWithFlags(&evV, cudaEventDisableTiming);
    }

    // ---- fork: FFN/wo weight conversions on side stream
    cudaEventRecord(evF, 0);
    cudaStreamWaitEvent(sB, evF, 0);
    convT<<<dim3(DD / 64, DD / 64), 256, 0, sB>>>(wo, woT_h, woT_l, DD, DD, 0, 0, 1, 0);
    convT<<<dim3(FFD / 64, DD / 64), 256, 0, sB>>>(w1f, w13T_h, w13T_l, DD, FFD, 0, 0, 2, 0);
    convT<<<dim3(FFD / 64, DD / 64), 256, 0, sB>>>(w3f, w13T_h, w13T_l, DD, FFD, 0, 0, 2, 1);
    convT<<<dim3(DD / 64, FFD / 64), 256, 0, sB>>>(w2f, w2fT_h, w2fT_l, FFD, DD, 0, 0, 1, 0);
    cudaEventRecord(evJ, sB);

    // ---- main stream: attention-path conversions + pipeline
    convT<<<dim3(3 * DD / 64, DD / 64), 256>>>(wqkv, wallT_h, wallT_l, DD, 3 * DD, 0, 0, 1, 0);
    convT<<<dim3(256 / 64, DD / 64), 256>>>(dw1, wallT_h + (size_t)3 * DD * DD,
                                            wallT_l + (size_t)3 * DD * DD, DD, 256, 0, 0, 1, 0);
    convT<<<dim3(64 / 64, DD / 64), 256>>>(dd, wallT_h + (size_t)(3 * DD + 256) * DD,
                                           wallT_l + (size_t)(3 * DD + 256) * DD, DD, 64, 0, 0, 1, 0);

    // 1. hn = rmsnorm(x) -> split act
    rmsnorm_split<<<TT, 256>>>(x, attn_nw, act_h, act_l, DD);
    // 2. [qkv | dwh | ddv] = hn @ [wqkv | dw1 | dd]   (one merged GEMM)
    mma_gemm<0><<<dim3(QKD / 128, TT / 128), 256, MM_SMEM>>>(
        act_h, act_l, wallT_h, wallT_l, qkvb, nullptr, nullptr, nullptr,
        TT, QKD, DD, QKD, 0, 0, 0, 0);
    cudaEventRecord(evA, 0);            // qkvb ready (for wproj on side stream)
    // wproj hides under the logits GEMM
    cudaStreamWaitEvent(sB, evA, 0);
    wproj_k<<<TT, 256, 0, sB>>>(qkvb + 3 * DD, qkw, w);
    cudaEventRecord(evW, sB);
    // 3. split + head rmsnorm + rope ; v transpose-split moves to side stream
    qkv_prep<<<dim3(NHH, TT), 128>>>(qkvb, q_nw, k_nw, qh, ql, kh, kl, v);
    cudaEventRecord(evB, 0);            // v ready
    cudaStreamWaitEvent(sB, evB, 0);
    convT<<<dim3(DHH / 64, TT / 64, NHH), 256, 0, sB>>>(v, vT_h, vT_l, TT, DHH,
        (long long)TT * DHH, (long long)DHH * TT, 1, 0);
    cudaEventRecord(evV, sB);
    // 5. logits = q @ k^T (causal tiles only)
    mma_gemm<1><<<dim3(TT / 128, TT / 128, NHH), 256, MM_SMEM>>>(
        qh, ql, kh, kl, lg, nullptr, nullptr, nullptr, TT, TT, DHH, SS,
        (long long)TT * DHH, (long long)TT * DHH, (long long)TT * SS, 0);
    // 6-8. cross_head pre (needs w), softmax, cross_head post -> ph/pl
    cudaStreamWaitEvent(0, evW, 0);
    crosshead_k<0><<<dim3(SS / 32, TT / 32), 256>>>(
        lg, w, qkvb + 3 * DD + 256, 0, 1, 0, 16, nullptr, nullptr);
    softmax_causal<<<dim3(TT, NHH), 256>>>(lg);
    crosshead_k<1><<<dim3(SS / 32, TT / 32), 256>>>(
        lg, w, qkvb + 3 * DD + 256, 2, 3, 32, 48, ph, pl);
    // 9. o = probs @ v (needs vT), 4-way split-K, then combine
    cudaStreamWaitEvent(0, evV, 0);
    mma_gemm<4><<<dim3(4, TT / 128, NHH), 256, MM_SMEM>>>(
        ph, pl, vT_h, vT_l, lg, nullptr, nullptr, nullptr, TT, DHH, TT, DHH,
        (long long)TT * SS, (long long)DHH * TT, (long long)TT * DHH,
        (long long)NHH * TT * DHH);
    pv_combine<<<(int)(((long long)NHH * TT * DHH + 255) / 256), 256>>>(lg, act_h, act_l);

    // ---- join side stream (FFN/wo weights) before consumption
    cudaStreamWaitEvent(0, evJ, 0);

    // 10. h = x + o @ wo
    mma_gemm<0><<<dim3(DD / 128, TT / 128), 256, MM_SMEM>>>(
        act_h, act_l, woT_h, woT_l, h, x, nullptr, nullptr, TT, DD, DD, DD, 0, 0, 0, 0);
    // 11. ffn: rmsnorm->split(act), interleaved w1|w3 gemm + fused swiglu
    //     -> split act2 (ph/pl scratch, DISJOINT from A), then w2 gemm
    rmsnorm_split<<<TT, 256>>>(h, ffn_nw, act_h, act_l, DD);
    mma_gemm<3><<<dim3(2 * FFD / 128, TT / 128), 256, MM_SMEM>>>(
        act_h, act_l, w13T_h, w13T_l, nullptr, nullptr, ph, pl,
        TT, 2 * FFD, DD, FFD, 0, 0, 0, 0);
    mma_gemm<0><<<dim3(DD / 128, TT / 128), 256, MM_SMEM>>>(
        ph, pl, w2fT_h, w2fT_l, out, h, nullptr, nullptr, TT, DD, FFD, DD, 0, 0, 0, 0);
}